// round 7
// baseline (speedup 1.0000x reference)
#include <cuda_runtime.h>
#include <cuda_bf16.h>
#include <cuda_fp16.h>
#include <cstdint>

#define B_    4
#define N_    2048
#define FIN_  512
#define FOUT_ 128
#define ROWS_TOT (B_ * N_)
#define PX    144    // X tile pitch: 64 bf16 = 128B + 16 pad
#define PW    272    // W tile pitch: 128 bf16 = 256B + 16 pad
#define PB2   144    // attn B tile pitch
#define TROWS 136    // o-rows in hE/hF: 128 data + 1 sums + 7 zero pad
#define TILE_B (TROWS * PB2)   // 19584

// ---------------- global scratch (no cudaMalloc allowed) --------------------
__device__ __align__(16) __nv_bfloat16 g_WH[FIN_ * FOUT_];  // W hi [k][n]
__device__ __align__(16) __nv_bfloat16 g_WL[FIN_ * FOUT_];  // W lo [k][n]
__device__ __align__(16) __half g_hE[B_ * TROWS * N_];  // [b][o][j] E2[j]*h; row128=E2; 129+=0
__device__ __align__(16) __half g_hF[B_ * TROWS * N_];  // F2 variant
__device__ float g_t1[ROWS_TOT], g_t2[ROWS_TOT];
__device__ float g_E1[ROWS_TOT], g_F1[ROWS_TOT];

// ---------------- helpers ----------------------------------------------------
__device__ __forceinline__ void mma_bf16(float* c,
    uint32_t a0, uint32_t a1, uint32_t a2, uint32_t a3, uint32_t b0, uint32_t b1) {
    asm volatile(
        "mma.sync.aligned.m16n8k16.row.col.f32.bf16.bf16.f32 "
        "{%0,%1,%2,%3},{%4,%5,%6,%7},{%8,%9},{%0,%1,%2,%3};"
        : "+f"(c[0]), "+f"(c[1]), "+f"(c[2]), "+f"(c[3])
        : "r"(a0), "r"(a1), "r"(a2), "r"(a3), "r"(b0), "r"(b1));
}
__device__ __forceinline__ void mma_f16(float* c,
    uint32_t a0, uint32_t a1, uint32_t a2, uint32_t a3, uint32_t b0, uint32_t b1) {
    asm volatile(
        "mma.sync.aligned.m16n8k16.row.col.f32.f16.f16.f32 "
        "{%0,%1,%2,%3},{%4,%5,%6,%7},{%8,%9},{%0,%1,%2,%3};"
        : "+f"(c[0]), "+f"(c[1]), "+f"(c[2]), "+f"(c[3])
        : "r"(a0), "r"(a1), "r"(a2), "r"(a3), "r"(b0), "r"(b1));
}
#define LDM4(r0, r1, r2, r3, a)                                          \
    asm volatile("ldmatrix.sync.aligned.m8n8.x4.shared.b16 "             \
                 "{%0,%1,%2,%3},[%4];"                                   \
                 : "=r"(r0), "=r"(r1), "=r"(r2), "=r"(r3) : "r"(a))
#define LDM4T(r0, r1, r2, r3, a)                                         \
    asm volatile("ldmatrix.sync.aligned.m8n8.x4.trans.shared.b16 "       \
                 "{%0,%1,%2,%3},[%4];"                                   \
                 : "=r"(r0), "=r"(r1), "=r"(r2), "=r"(r3) : "r"(a))
__device__ __forceinline__ uint32_t bf2u(__nv_bfloat162 v) {
    return *reinterpret_cast<uint32_t*>(&v);
}
__device__ __forceinline__ void split2(float a, float b, uint32_t& hi, uint32_t& lo) {
    __nv_bfloat162 h = __floats2bfloat162_rn(a, b);
    __nv_bfloat162 l = __floats2bfloat162_rn(a - __bfloat162float(h.x),
                                             b - __bfloat162float(h.y));
    hi = bf2u(h); lo = bf2u(l);
}
__device__ __forceinline__ uint32_t h2u(__half2 v) {
    return *reinterpret_cast<uint32_t*>(&v);
}
__device__ __forceinline__ uint32_t bpack(bool e0, bool e1) {
    return (e0 ? 0x3C00u : 0u) | (e1 ? 0x3C000000u : 0u);
}
#define CPASYNC16(dst, src) \
    asm volatile("cp.async.cg.shared.global [%0], [%1], 16;" :: "r"(dst), "l"(src))
#define CPCOMMIT() asm volatile("cp.async.commit_group;" ::: "memory")
#define CPWAIT(n)  asm volatile("cp.async.wait_group %0;" :: "n"(n) : "memory")
__device__ __forceinline__ uint32_t smem_u32(const void* p) {
    uint32_t a;
    asm("{ .reg .u64 t; cvta.to.shared.u64 t, %1; cvt.u32.u64 %0, t; }"
        : "=r"(a) : "l"(p));
    return a;
}

// ---------------------------------------------------------------------------
// K0: W fp32 [k][n] -> bf16 hi/lo [k][n] (one-shot split; layout unchanged)
// ---------------------------------------------------------------------------
__global__ __launch_bounds__(256) void k_wprep(const float* __restrict__ W) {
    int f = blockIdx.x * 256 + threadIdx.x;   // 16384 float4 total
    float4 v = *(const float4*)(W + f * 4);
    uint32_t h0, l0, h1, l1;
    split2(v.x, v.y, h0, l0);
    split2(v.z, v.w, h1, l1);
    *(uint2*)(g_WH + f * 4) = make_uint2(h0, h1);
    *(uint2*)(g_WL + f * 4) = make_uint2(l0, l1);
}

// ---------------------------------------------------------------------------
// K1: h = X @ W (bf16 hi/lo 3-MMA). 32 rows/CTA, 128 thr, grid 256.
// X stored [m][k] (ldmatrix), W pre-split, cp.async'd [k][n] (ldmatrix.trans).
// Epilogue: t1/t2, E/F, and hE/hF fp16 [o][j] incl. sums row o=128.
// ---------------------------------------------------------------------------
#define GXH 0
#define GXL 4608
#define GWH 9216
#define GWL 26624
#define GA1 44032
#define GA2 44544
#define GE2 45056
#define GF2 45312
#define GSM 45568

__global__ __launch_bounds__(128) void k_gemm_tc(const float* __restrict__ X,
                                                 const float* __restrict__ a1,
                                                 const float* __restrict__ a2) {
    extern __shared__ char sm[];
    const uint32_t smb = smem_u32(sm);
    const int t = threadIdx.x, w = t >> 5, lane = t & 31;
    const int wm = w & 1, wn = w >> 1;
    const int row0 = blockIdx.x * 32;

    ((float*)(sm + GA1))[t] = a1[t];
    ((float*)(sm + GA2))[t] = a2[t];

    float acc[8][4];
#pragma unroll
    for (int nt = 0; nt < 8; nt++)
        acc[nt][0] = acc[nt][1] = acc[nt][2] = acc[nt][3] = 0.f;

    const uint32_t ax_off =
        (uint32_t)(wm * 16 + ((lane >> 3) & 1) * 8 + (lane & 7)) * PX +
        (lane >> 4) * 16;
    const uint32_t wl_row = (uint32_t)lane * PW;

    for (int c = 0; c < 8; c++) {
        const int kc = c * 64;
        // W tiles via cp.async: 64 k x 16 vec x 2 mats = 2048 vec / 128 thr
#pragma unroll
        for (int l = 0; l < 16; l++) {
            int f = t + l * 128;
            int mat = f >= 1024;
            int idx = f - (mat ? 1024 : 0);
            int k = idx >> 4, u = idx & 15;
            const __nv_bfloat16* src = (mat ? g_WL : g_WH) +
                                       (size_t)(kc + k) * FOUT_ + u * 8;
            uint32_t dst = smb + (mat ? GWL : GWH) + k * PW + u * 16;
            CPASYNC16(dst, src);
        }
        CPCOMMIT();
        // X tile: [32 m][64 k] fp32 -> bf16 hi/lo, stored [m][k]
#pragma unroll
        for (int l = 0; l < 4; l++) {
            int f = t + l * 128;
            int m = f >> 4, kq = (f & 15) * 4;
            float4 v = *(const float4*)(X + (size_t)(row0 + m) * FIN_ + kc + kq);
            uint32_t h0, l0, h1, l1;
            split2(v.x, v.y, h0, l0);
            split2(v.z, v.w, h1, l1);
            *(uint2*)(sm + GXH + m * PX + kq * 2) = make_uint2(h0, h1);
            *(uint2*)(sm + GXL + m * PX + kq * 2) = make_uint2(l0, l1);
        }
        CPWAIT(0);
        __syncthreads();

        uint32_t ah[4][4], al[4][4];
#pragma unroll
        for (int ks = 0; ks < 4; ks++) {
            LDM4(ah[ks][0], ah[ks][1], ah[ks][2], ah[ks][3],
                 smb + GXH + ax_off + ks * 32);
            LDM4(al[ks][0], al[ks][1], al[ks][2], al[ks][3],
                 smb + GXL + ax_off + ks * 32);
        }
#pragma unroll
        for (int nt = 0; nt < 8; nt++) {
            const int n0 = wn * 64 + nt * 8;
            const uint32_t wadr = smb + GWH + wl_row + n0 * 2;
            uint32_t bh[8], bl[8];
            LDM4T(bh[0], bh[1], bh[2], bh[3], wadr);
            LDM4T(bh[4], bh[5], bh[6], bh[7], wadr + 32 * PW);
            LDM4T(bl[0], bl[1], bl[2], bl[3], wadr + (GWL - GWH));
            LDM4T(bl[4], bl[5], bl[6], bl[7], wadr + (GWL - GWH) + 32 * PW);
#pragma unroll
            for (int ks = 0; ks < 4; ks++) {
                mma_bf16(acc[nt], ah[ks][0], ah[ks][1], ah[ks][2], ah[ks][3],
                         bh[2 * ks], bh[2 * ks + 1]);
                mma_bf16(acc[nt], ah[ks][0], ah[ks][1], ah[ks][2], ah[ks][3],
                         bl[2 * ks], bl[2 * ks + 1]);
                mma_bf16(acc[nt], al[ks][0], al[ks][1], al[ks][2], al[ks][3],
                         bh[2 * ks], bh[2 * ks + 1]);
            }
        }
        __syncthreads();
    }

    // ---- epilogue ----
    const int g = lane >> 2, tig = lane & 3;
    float* Ds = (float*)sm;   // [32][132] f32 = 16896 B (< GA1; tables intact)
    {
        const int r = wm * 16 + g, cl = wn * 64 + 2 * tig;
#pragma unroll
        for (int nt = 0; nt < 8; nt++) {
            Ds[r * 132 + cl + nt * 8]           = acc[nt][0];
            Ds[r * 132 + cl + nt * 8 + 1]       = acc[nt][1];
            Ds[(r + 8) * 132 + cl + nt * 8]     = acc[nt][2];
            Ds[(r + 8) * 132 + cl + nt * 8 + 1] = acc[nt][3];
        }
    }
    __syncthreads();
    const float* A1 = (const float*)(sm + GA1);
    const float* A2 = (const float*)(sm + GA2);
    float* E2s = (float*)(sm + GE2);
    float* F2s = (float*)(sm + GF2);
#pragma unroll
    for (int rr = 0; rr < 8; rr++) {
        int r = w * 8 + rr;
        float s1 = 0.f, s2 = 0.f;
#pragma unroll
        for (int q = 0; q < 4; q++) {
            float v = Ds[r * 132 + lane + 32 * q];
            s1 = fmaf(v, A1[lane + 32 * q], s1);
            s2 = fmaf(v, A2[lane + 32 * q], s2);
        }
#pragma unroll
        for (int o = 16; o; o >>= 1) {
            s1 += __shfl_down_sync(0xffffffffu, s1, o);
            s2 += __shfl_down_sync(0xffffffffu, s2, o);
        }
        if (lane == 0) {
            int gr = row0 + r;
            g_t1[gr] = s1;  g_t2[gr] = s2;
            g_E1[gr] = expf(s1);          g_F1[gr] = expf(0.2f * s1);
            E2s[r] = expf(s2);            F2s[r] = expf(0.2f * s2);
        }
    }
    __syncthreads();
    {
        const int o = t;                        // 0..127
        const int bb = row0 >> 11, j0g = row0 & (N_ - 1);
        uint32_t uE[16], uF[16];
#pragma unroll
        for (int ii = 0; ii < 16; ii++) {
            int j0l = 2 * ii;
            float v0 = Ds[j0l * 132 + o], v1 = Ds[(j0l + 1) * 132 + o];
            uE[ii] = h2u(__floats2half2_rn(v0 * E2s[j0l], v1 * E2s[j0l + 1]));
            uF[ii] = h2u(__floats2half2_rn(v0 * F2s[j0l], v1 * F2s[j0l + 1]));
        }
        size_t base = ((size_t)(bb * TROWS) + o) * N_ + j0g;
#pragma unroll
        for (int q = 0; q < 4; q++) {
            *(uint4*)(g_hE + base + q * 8) =
                make_uint4(uE[4 * q], uE[4 * q + 1], uE[4 * q + 2], uE[4 * q + 3]);
            *(uint4*)(g_hF + base + q * 8) =
                make_uint4(uF[4 * q], uF[4 * q + 1], uF[4 * q + 2], uF[4 * q + 3]);
        }
        if (t < 32) {
            size_t sbase = ((size_t)(bb * TROWS) + 128) * N_ + j0g + t;
            g_hE[sbase] = __float2half_rn(E2s[t]);
            g_hF[sbase] = __float2half_rn(F2s[t]);
        }
    }
}

// ---------------------------------------------------------------------------
// K2: attention via binary-mask GEMMs, ldmatrix B-frags.
// 32 i-rows/CTA, 128 thr (4 warps: wm 2 x wn 2), grid 256, 2 CTA/SM.
//   D = diag(E1)*(Mpos @ hE) + diag(F1)*(Mneg @ hF),  sums in col 128.
// ---------------------------------------------------------------------------
#define AT2  (4 * TILE_B)           // 78336: T2 floats [2048]
#define ADEN (AT2 + 8192)           // 86528: denominators [32]
#define ASM  (ADEN + 256)           // 86784 total

__global__ __launch_bounds__(128) void k_attn_tc(const int* __restrict__ adj,
                                                 const int* __restrict__ d1p,
                                                 const int* __restrict__ d2p,
                                                 float* __restrict__ out) {
    extern __shared__ char sm[];
    const uint32_t smb = smem_u32(sm);
    const int t = threadIdx.x, w = t >> 5, lane = t & 31;
    const int g = lane >> 2, tig = lane & 3;
    const int wm = w & 1, wn = w >> 1;
    const int b = blockIdx.x >> 6, i0 = (blockIdx.x & 63) * 32;
    const int d1 = *d1p, d2 = *d2p;

    float* T2 = (float*)(sm + AT2);
#pragma unroll
    for (int l = 0; l < 4; l++) {
        int f = t + l * 128;
        ((float4*)T2)[f] = ((const float4*)(g_t2 + b * N_))[f];
    }

    const int r0 = i0 + wm * 16 + g, r1 = r0 + 8;
    const int gr0 = b * N_ + r0, gr1 = b * N_ + r1;
    const float nt10 = -g_t1[gr0], E10 = g_E1[gr0], F10 = g_F1[gr0];
    const float nt11 = -g_t1[gr1], E11 = g_E1[gr1], F11 = g_F1[gr1];
    const size_t ab0 = (size_t)gr0 * N_, ab1 = (size_t)gr1 * N_;
    const __half* gEb = g_hE + (size_t)b * TROWS * N_;
    const __half* gFb = g_hF + (size_t)b * TROWS * N_;

    float accE[9][4], accF[9][4];
#pragma unroll
    for (int nt = 0; nt < 9; nt++)
#pragma unroll
        for (int q = 0; q < 4; q++) { accE[nt][q] = 0.f; accF[nt][q] = 0.f; }

    // cp.async: 136 rows x 8 vec x 2 mats = 2176 / 128 thr = 17 each
    auto load_chunk = [&](int j0, int buf) {
#pragma unroll
        for (int l = 0; l < 17; l++) {
            int f = t + l * 128;
            int mat = f >= 1088;
            int idx = f - (mat ? 1088 : 0);
            int row = idx >> 3, u = idx & 7;
            const __half* src = (mat ? gFb : gEb) + (size_t)row * N_ + j0 + u * 8;
            uint32_t dst = smb + buf * (2 * TILE_B) + mat * TILE_B + row * PB2 + u * 16;
            CPASYNC16(dst, src);
        }
    };

    load_chunk(0, 0);
    CPCOMMIT();

    const int nbase = wn ? 72 : 0;
    const uint32_t bloff = (uint32_t)(lane & 7) * PB2 + (lane >> 3) * 16;

    for (int c = 0; c < 32; c++) {
        const int buf = c & 1;
        __syncthreads();
        if (c + 1 < 32) {
            load_chunk((c + 1) * 64, buf ^ 1);
            CPCOMMIT();
            CPWAIT(1);
        } else {
            CPWAIT(0);
        }
        __syncthreads();

        const int j0 = c * 64;
        uint32_t aE[4][4], aF[4][4];
#pragma unroll
        for (int ks = 0; ks < 4; ks++) {
            const int c0 = j0 + ks * 16 + 2 * tig;
            int2 a00 = *(const int2*)(adj + ab0 + c0);
            int2 a01 = *(const int2*)(adj + ab0 + c0 + 8);
            int2 a10 = *(const int2*)(adj + ab1 + c0);
            int2 a11 = *(const int2*)(adj + ab1 + c0 + 8);
            float2 t2a = *(const float2*)(T2 + c0);
            float2 t2b = *(const float2*)(T2 + c0 + 8);

            bool m00 = (a00.x == d1) | (a00.x == d2);
            bool m01 = (a00.y == d1) | (a00.y == d2);
            bool m02 = (a01.x == d1) | (a01.x == d2);
            bool m03 = (a01.y == d1) | (a01.y == d2);
            bool m10 = (a10.x == d1) | (a10.x == d2);
            bool m11 = (a10.y == d1) | (a10.y == d2);
            bool m12 = (a11.x == d1) | (a11.x == d2);
            bool m13 = (a11.y == d1) | (a11.y == d2);
            bool p0a = t2a.x > nt10, p0b = t2a.y > nt10;
            bool p0c = t2b.x > nt10, p0d = t2b.y > nt10;
            bool p1a = t2a.x > nt11, p1b = t2a.y > nt11;
            bool p1c = t2b.x > nt11, p1d = t2b.y > nt11;

            aE[ks][0] = bpack(m00 && p0a, m01 && p0b);
            aE[ks][1] = bpack(m10 && p1a, m11 && p1b);
            aE[ks][2] = bpack(m02 && p0c, m03 && p0d);
            aE[ks][3] = bpack(m12 && p1c, m13 && p1d);
            aF[ks][0] = bpack(m00 && !p0a, m01 && !p0b);
            aF[ks][1] = bpack(m10 && !p1a, m11 && !p1b);
            aF[ks][2] = bpack(m02 && !p0c, m03 && !p0d);
            aF[ks][3] = bpack(m12 && !p1c, m13 && !p1d);
        }

        const uint32_t base = smb + buf * (2 * TILE_B);
#define MMA_TILE(NT, N0)                                                      \
        {                                                                     \
            const uint32_t ae = base + (uint32_t)(N0) * PB2 + bloff;          \
            uint32_t bE[8], bF[8];                                            \
            LDM4(bE[0], bE[1], bE[2], bE[3], ae);                             \
            LDM4(bE[4], bE[5], bE[6], bE[7], ae + 64);                        \
            LDM4(bF[0], bF[1], bF[2], bF[3], ae + TILE_B);                    \
            LDM4(bF[4], bF[5], bF[6], bF[7], ae + TILE_B + 64);               \
            _Pragma("unroll")                                                 \
            for (int ks = 0; ks < 4; ks++) {                                  \
                mma_f16(accE[NT], aE[ks][0], aE[ks][1], aE[ks][2], aE[ks][3], \
                        bE[2 * ks], bE[2 * ks + 1]);                          \
                mma_f16(accF[NT], aF[ks][0], aF[ks][1], aF[ks][2], aF[ks][3], \
                        bF[2 * ks], bF[2 * ks + 1]);                          \
            }                                                                 \
        }
#pragma unroll
        for (int nt = 0; nt < 8; nt++) MMA_TILE(nt, nbase + nt * 8);
        if (!wn) MMA_TILE(8, 64);
#undef MMA_TILE
    }

    // denominators: col 128 lives in wn1 tile nt=7 (n0=128), col elem 0/2
    float* den = (float*)(sm + ADEN);
    if (wn == 1 && tig == 0) {
        den[wm * 16 + g]     = E10 * accE[7][0] + F10 * accF[7][0];
        den[wm * 16 + g + 8] = E11 * accE[7][2] + F11 * accF[7][2];
    }
    __syncthreads();
    const float inv0 = 1.0f / den[wm * 16 + g];
    const float inv1 = 1.0f / den[wm * 16 + g + 8];

#pragma unroll
    for (int nt = 0; nt < 9; nt++) {
        if (wn == 1 && nt >= 7) break;     // nt7 = sums/pad tile
        const int cl = nbase + nt * 8 + 2 * tig;
        *(float2*)(out + (size_t)gr0 * FOUT_ + cl) =
            make_float2((E10 * accE[nt][0] + F10 * accF[nt][0]) * inv0,
                        (E10 * accE[nt][1] + F10 * accF[nt][1]) * inv0);
        *(float2*)(out + (size_t)gr1 * FOUT_ + cl) =
            make_float2((E11 * accE[nt][2] + F11 * accF[nt][2]) * inv1,
                        (E11 * accE[nt][3] + F11 * accF[nt][3]) * inv1);
    }
}

// ---------------------------------------------------------------------------
extern "C" void kernel_launch(void* const* d_in, const int* in_sizes, int n_in,
                              void* d_out, int out_size) {
    const float* X   = (const float*)d_in[0];
    const float* W   = (const float*)d_in[1];
    const float* a1  = (const float*)d_in[2];
    const float* a2  = (const float*)d_in[3];
    const int*   adj = (const int*)d_in[4];
    // d_in[5] = adj_tree: unused by the reference forward
    const int* d1p = (const int*)d_in[6];
    const int* d2p = (const int*)d_in[7];
    float* out = (float*)d_out;

    k_wprep<<<FIN_ * FOUT_ / 4 / 256, 256>>>(W);

    cudaFuncSetAttribute(k_gemm_tc, cudaFuncAttributeMaxDynamicSharedMemorySize, GSM);
    k_gemm_tc<<<ROWS_TOT / 32, 128, GSM>>>(X, a1, a2);

    cudaFuncSetAttribute(k_attn_tc, cudaFuncAttributeMaxDynamicSharedMemorySize, ASM);
    k_attn_tc<<<B_ * (N_ / 32), 128, ASM>>>(adj, d1p, d2p, out);
}

// round 8
// speedup vs baseline: 1.2163x; 1.2163x over previous
#include <cuda_runtime.h>
#include <cuda_bf16.h>
#include <cuda_fp16.h>
#include <cstdint>

#define B_    4
#define N_    2048
#define FIN_  512
#define FOUT_ 128
#define ROWS_TOT (B_ * N_)
#define PX    144    // X tile pitch: 64 bf16 = 128B + 16 pad
#define PW    272    // W tile pitch: 128 bf16 = 256B + 16 pad
#define PB2   144    // attn B tile pitch
#define TROWS 136    // o-rows in hE/hF: 128 data + 1 sums + 7 zero pad
#define TILE_B (TROWS * PB2)   // 19584

// ---------------- global scratch (no cudaMalloc allowed) --------------------
__device__ __align__(16) __half g_hE[B_ * TROWS * N_];  // [b][o][j] E2[j]*h; row128=E2
__device__ __align__(16) __half g_hF[B_ * TROWS * N_];  // F2 variant
__device__ float g_t1[ROWS_TOT], g_t2[ROWS_TOT];
__device__ float g_E1[ROWS_TOT], g_F1[ROWS_TOT];
__device__ __align__(16) float g_part[2][ROWS_TOT * FOUT_];  // j-half partials, 8 MB
__device__ float g_den[2][ROWS_TOT];
__device__ int   g_cnt[B_ * 32];                              // per-i-tile arrival

// ---------------- helpers ----------------------------------------------------
__device__ __forceinline__ void mma_bf16(float* c,
    uint32_t a0, uint32_t a1, uint32_t a2, uint32_t a3, uint32_t b0, uint32_t b1) {
    asm volatile(
        "mma.sync.aligned.m16n8k16.row.col.f32.bf16.bf16.f32 "
        "{%0,%1,%2,%3},{%4,%5,%6,%7},{%8,%9},{%0,%1,%2,%3};"
        : "+f"(c[0]), "+f"(c[1]), "+f"(c[2]), "+f"(c[3])
        : "r"(a0), "r"(a1), "r"(a2), "r"(a3), "r"(b0), "r"(b1));
}
__device__ __forceinline__ void mma_f16(float* c,
    uint32_t a0, uint32_t a1, uint32_t a2, uint32_t a3, uint32_t b0, uint32_t b1) {
    asm volatile(
        "mma.sync.aligned.m16n8k16.row.col.f32.f16.f16.f32 "
        "{%0,%1,%2,%3},{%4,%5,%6,%7},{%8,%9},{%0,%1,%2,%3};"
        : "+f"(c[0]), "+f"(c[1]), "+f"(c[2]), "+f"(c[3])
        : "r"(a0), "r"(a1), "r"(a2), "r"(a3), "r"(b0), "r"(b1));
}
#define LDM4(r0, r1, r2, r3, a)                                          \
    asm volatile("ldmatrix.sync.aligned.m8n8.x4.shared.b16 "             \
                 "{%0,%1,%2,%3},[%4];"                                   \
                 : "=r"(r0), "=r"(r1), "=r"(r2), "=r"(r3) : "r"(a))
#define LDM4T(r0, r1, r2, r3, a)                                         \
    asm volatile("ldmatrix.sync.aligned.m8n8.x4.trans.shared.b16 "       \
                 "{%0,%1,%2,%3},[%4];"                                   \
                 : "=r"(r0), "=r"(r1), "=r"(r2), "=r"(r3) : "r"(a))
__device__ __forceinline__ uint32_t bf2u(__nv_bfloat162 v) {
    return *reinterpret_cast<uint32_t*>(&v);
}
__device__ __forceinline__ void split2(float a, float b, uint32_t& hi, uint32_t& lo) {
    __nv_bfloat162 h = __floats2bfloat162_rn(a, b);
    __nv_bfloat162 l = __floats2bfloat162_rn(a - __bfloat162float(h.x),
                                             b - __bfloat162float(h.y));
    hi = bf2u(h); lo = bf2u(l);
}
__device__ __forceinline__ uint32_t h2u(__half2 v) {
    return *reinterpret_cast<uint32_t*>(&v);
}
__device__ __forceinline__ uint32_t bpack(bool e0, bool e1) {
    return (e0 ? 0x3C00u : 0u) | (e1 ? 0x3C000000u : 0u);
}
#define CPASYNC16(dst, src) \
    asm volatile("cp.async.cg.shared.global [%0], [%1], 16;" :: "r"(dst), "l"(src))
#define CPCOMMIT() asm volatile("cp.async.commit_group;" ::: "memory")
#define CPWAIT(n)  asm volatile("cp.async.wait_group %0;" :: "n"(n) : "memory")
__device__ __forceinline__ uint32_t smem_u32(const void* p) {
    uint32_t a;
    asm("{ .reg .u64 t; cvta.to.shared.u64 t, %1; cvt.u32.u64 %0, t; }"
        : "=r"(a) : "l"(p));
    return a;
}

// ---------------------------------------------------------------------------
// K1: h = X @ W (bf16 hi/lo 3-MMA), W split inline (R6 version, verbatim).
// ---------------------------------------------------------------------------
#define GXH 0
#define GXL 9216
#define GWH 18432
#define GWL 35840
#define GA1 53248
#define GA2 53760
#define GE2 54272
#define GF2 54528
#define GSM 54784

__global__ __launch_bounds__(256) void k_gemm_tc(const float* __restrict__ X,
                                                 const float* __restrict__ W,
                                                 const float* __restrict__ a1,
                                                 const float* __restrict__ a2) {
    extern __shared__ char sm[];
    const uint32_t smb = smem_u32(sm);
    const int t = threadIdx.x, w = t >> 5, lane = t & 31;
    const int wm = w & 3, wn = w >> 2;
    const int row0 = blockIdx.x * 64;

    if (t < 128) {
        ((float*)(sm + GA1))[t] = a1[t];
        ((float*)(sm + GA2))[t] = a2[t];
    }

    float acc[8][4];
#pragma unroll
    for (int nt = 0; nt < 8; nt++)
        acc[nt][0] = acc[nt][1] = acc[nt][2] = acc[nt][3] = 0.f;

    const uint32_t ax_off =
        (uint32_t)(wm * 16 + ((lane >> 3) & 1) * 8 + (lane & 7)) * PX +
        (lane >> 4) * 16;
    const uint32_t wl_row = (uint32_t)lane * PW;

    for (int c = 0; c < 8; c++) {
        const int kc = c * 64;
#pragma unroll
        for (int l = 0; l < 4; l++) {
            int f = t + l * 256;
            int m = f >> 4, kq = (f & 15) * 4;
            float4 v = *(const float4*)(X + (size_t)(row0 + m) * FIN_ + kc + kq);
            uint32_t h0, l0, h1, l1;
            split2(v.x, v.y, h0, l0);
            split2(v.z, v.w, h1, l1);
            *(uint2*)(sm + GXH + m * PX + kq * 2) = make_uint2(h0, h1);
            *(uint2*)(sm + GXL + m * PX + kq * 2) = make_uint2(l0, l1);
        }
#pragma unroll
        for (int l = 0; l < 8; l++) {
            int f = t + l * 256;
            int k = f >> 5, nq = (f & 31) * 4;
            float4 v = *(const float4*)(W + (size_t)(kc + k) * FOUT_ + nq);
            uint32_t h0, l0, h1, l1;
            split2(v.x, v.y, h0, l0);
            split2(v.z, v.w, h1, l1);
            *(uint2*)(sm + GWH + k * PW + nq * 2) = make_uint2(h0, h1);
            *(uint2*)(sm + GWL + k * PW + nq * 2) = make_uint2(l0, l1);
        }
        __syncthreads();

        uint32_t ah[4][4], al[4][4];
#pragma unroll
        for (int ks = 0; ks < 4; ks++) {
            LDM4(ah[ks][0], ah[ks][1], ah[ks][2], ah[ks][3],
                 smb + GXH + ax_off + ks * 32);
            LDM4(al[ks][0], al[ks][1], al[ks][2], al[ks][3],
                 smb + GXL + ax_off + ks * 32);
        }
#pragma unroll
        for (int nt = 0; nt < 8; nt++) {
            const int n0 = wn * 64 + nt * 8;
            const uint32_t wadr = smb + GWH + wl_row + n0 * 2;
            uint32_t bh[8], bl[8];
            LDM4T(bh[0], bh[1], bh[2], bh[3], wadr);
            LDM4T(bh[4], bh[5], bh[6], bh[7], wadr + 32 * PW);
            LDM4T(bl[0], bl[1], bl[2], bl[3], wadr + (GWL - GWH));
            LDM4T(bl[4], bl[5], bl[6], bl[7], wadr + (GWL - GWH) + 32 * PW);
#pragma unroll
            for (int ks = 0; ks < 4; ks++) {
                mma_bf16(acc[nt], ah[ks][0], ah[ks][1], ah[ks][2], ah[ks][3],
                         bh[2 * ks], bh[2 * ks + 1]);
                mma_bf16(acc[nt], ah[ks][0], ah[ks][1], ah[ks][2], ah[ks][3],
                         bl[2 * ks], bl[2 * ks + 1]);
                mma_bf16(acc[nt], al[ks][0], al[ks][1], al[ks][2], al[ks][3],
                         bh[2 * ks], bh[2 * ks + 1]);
            }
        }
        __syncthreads();
    }

    // ---- epilogue ----
    const int g = lane >> 2, tig = lane & 3;
    float* Ds = (float*)sm;
    {
        const int r = wm * 16 + g, cl = wn * 64 + 2 * tig;
#pragma unroll
        for (int nt = 0; nt < 8; nt++) {
            Ds[r * 132 + cl + nt * 8]           = acc[nt][0];
            Ds[r * 132 + cl + nt * 8 + 1]       = acc[nt][1];
            Ds[(r + 8) * 132 + cl + nt * 8]     = acc[nt][2];
            Ds[(r + 8) * 132 + cl + nt * 8 + 1] = acc[nt][3];
        }
    }
    __syncthreads();
    const float* A1 = (const float*)(sm + GA1);
    const float* A2 = (const float*)(sm + GA2);
    float* E2s = (float*)(sm + GE2);
    float* F2s = (float*)(sm + GF2);
#pragma unroll
    for (int rr = 0; rr < 8; rr++) {
        int r = w * 8 + rr;
        float s1 = 0.f, s2 = 0.f;
#pragma unroll
        for (int q = 0; q < 4; q++) {
            float v = Ds[r * 132 + lane + 32 * q];
            s1 = fmaf(v, A1[lane + 32 * q], s1);
            s2 = fmaf(v, A2[lane + 32 * q], s2);
        }
#pragma unroll
        for (int o = 16; o; o >>= 1) {
            s1 += __shfl_down_sync(0xffffffffu, s1, o);
            s2 += __shfl_down_sync(0xffffffffu, s2, o);
        }
        if (lane == 0) {
            int gr = row0 + r;
            g_t1[gr] = s1;  g_t2[gr] = s2;
            g_E1[gr] = expf(s1);          g_F1[gr] = expf(0.2f * s1);
            E2s[r] = expf(s2);            F2s[r] = expf(0.2f * s2);
        }
    }
    __syncthreads();
    {
        const int o = t & 127, half = t >> 7;
        const int bb = row0 >> 11, j0g = row0 & (N_ - 1);
        uint32_t uE[16], uF[16];
#pragma unroll
        for (int ii = 0; ii < 16; ii++) {
            int j0l = half * 32 + 2 * ii;
            float v0 = Ds[j0l * 132 + o], v1 = Ds[(j0l + 1) * 132 + o];
            uE[ii] = h2u(__floats2half2_rn(v0 * E2s[j0l], v1 * E2s[j0l + 1]));
            uF[ii] = h2u(__floats2half2_rn(v0 * F2s[j0l], v1 * F2s[j0l + 1]));
        }
        size_t base = ((size_t)(bb * TROWS) + o) * N_ + j0g + half * 32;
#pragma unroll
        for (int q = 0; q < 4; q++) {
            *(uint4*)(g_hE + base + q * 8) =
                make_uint4(uE[4 * q], uE[4 * q + 1], uE[4 * q + 2], uE[4 * q + 3]);
            *(uint4*)(g_hF + base + q * 8) =
                make_uint4(uF[4 * q], uF[4 * q + 1], uF[4 * q + 2], uF[4 * q + 3]);
        }
        if (t < 64) {
            size_t sbase = ((size_t)(bb * TROWS) + 128) * N_ + j0g + t;
            g_hE[sbase] = __float2half_rn(E2s[t]);
            g_hF[sbase] = __float2half_rn(F2s[t]);
        }
    }
}

// ---------------------------------------------------------------------------
// K2: attention, j-split x2 + in-kernel combine.
// grid 256 = (b,i-tile) x jhalf. 64 i-rows, 256 thr, 2 CTA/SM target.
// ---------------------------------------------------------------------------
#define AT2  (4 * TILE_B)           // 78336: T2 floats [2048]
#define ASM  (AT2 + 8192)           // 86528 total dynamic

__global__ __launch_bounds__(256, 2) void k_attn_tc(const int* __restrict__ adj,
                                                    const int* __restrict__ d1p,
                                                    const int* __restrict__ d2p,
                                                    float* __restrict__ out) {
    extern __shared__ char sm[];
    __shared__ float s_den[64];
    __shared__ int s_old;
    const uint32_t smb = smem_u32(sm);
    const int t = threadIdx.x, w = t >> 5, lane = t & 31;
    const int g = lane >> 2, tig = lane & 3;
    const int wm = w & 3, wn = w >> 2;
    const int tile = blockIdx.x >> 1, jh = blockIdx.x & 1;
    const int b = tile >> 5, i0 = (tile & 31) * 64;
    const int jbase = jh * 1024;
    const int d1 = *d1p, d2 = *d2p;

    float* T2 = (float*)(sm + AT2);
#pragma unroll
    for (int l = 0; l < 2; l++) {
        int f = t + l * 256;
        ((float4*)T2)[f] = ((const float4*)(g_t2 + b * N_))[f];
    }

    const int r0 = i0 + wm * 16 + g, r1 = r0 + 8;
    const int gr0 = b * N_ + r0, gr1 = b * N_ + r1;
    const float nt10 = -g_t1[gr0], E10 = g_E1[gr0], F10 = g_F1[gr0];
    const float nt11 = -g_t1[gr1], E11 = g_E1[gr1], F11 = g_F1[gr1];
    const size_t ab0 = (size_t)gr0 * N_, ab1 = (size_t)gr1 * N_;
    const __half* gEb = g_hE + (size_t)b * TROWS * N_;
    const __half* gFb = g_hF + (size_t)b * TROWS * N_;

    float accE[9][4], accF[9][4];
#pragma unroll
    for (int nt = 0; nt < 9; nt++)
#pragma unroll
        for (int q = 0; q < 4; q++) { accE[nt][q] = 0.f; accF[nt][q] = 0.f; }

    auto load_chunk = [&](int j0, int buf) {
#pragma unroll
        for (int l = 0; l < 9; l++) {
            int f = t + l * 256;
            if (f < 2176) {
                int mat = f >= 1088;
                int idx = f - (mat ? 1088 : 0);
                int row = idx >> 3, u = idx & 7;
                const __half* src = (mat ? gFb : gEb) + (size_t)row * N_ + j0 + u * 8;
                uint32_t dst = smb + buf * (2 * TILE_B) + mat * TILE_B + row * PB2 + u * 16;
                CPASYNC16(dst, src);
            }
        }
    };

    load_chunk(jbase, 0);
    CPCOMMIT();

    const int nbase = wn ? 72 : 0;
    const uint32_t bloff = (uint32_t)(lane & 7) * PB2 + (lane >> 3) * 16;

    for (int c = 0; c < 16; c++) {
        const int buf = c & 1;
        __syncthreads();
        if (c + 1 < 16) {
            load_chunk(jbase + (c + 1) * 64, buf ^ 1);
            CPCOMMIT();
            CPWAIT(1);
        } else {
            CPWAIT(0);
        }
        __syncthreads();

        const int j0 = jbase + c * 64;
        const uint32_t base = smb + buf * (2 * TILE_B);

#pragma unroll
        for (int ga = 0; ga < 2; ga++) {
            // ---- A frags for ks = 2ga, 2ga+1 ----
            uint32_t aE[2][4], aF[2][4];
#pragma unroll
            for (int k2 = 0; k2 < 2; k2++) {
                const int c0 = j0 + (ga * 2 + k2) * 16 + 2 * tig;
                int2 a00 = *(const int2*)(adj + ab0 + c0);
                int2 a01 = *(const int2*)(adj + ab0 + c0 + 8);
                int2 a10 = *(const int2*)(adj + ab1 + c0);
                int2 a11 = *(const int2*)(adj + ab1 + c0 + 8);
                float2 t2a = *(const float2*)(T2 + c0);
                float2 t2b = *(const float2*)(T2 + c0 + 8);

                bool m00 = (a00.x == d1) | (a00.x == d2);
                bool m01 = (a00.y == d1) | (a00.y == d2);
                bool m02 = (a01.x == d1) | (a01.x == d2);
                bool m03 = (a01.y == d1) | (a01.y == d2);
                bool m10 = (a10.x == d1) | (a10.x == d2);
                bool m11 = (a10.y == d1) | (a10.y == d2);
                bool m12 = (a11.x == d1) | (a11.x == d2);
                bool m13 = (a11.y == d1) | (a11.y == d2);
                bool p0a = t2a.x > nt10, p0b = t2a.y > nt10;
                bool p0c = t2b.x > nt10, p0d = t2b.y > nt10;
                bool p1a = t2a.x > nt11, p1b = t2a.y > nt11;
                bool p1c = t2b.x > nt11, p1d = t2b.y > nt11;

                aE[k2][0] = bpack(m00 && p0a, m01 && p0b);
                aE[k2][1] = bpack(m10 && p1a, m11 && p1b);
                aE[k2][2] = bpack(m02 && p0c, m03 && p0d);
                aE[k2][3] = bpack(m12 && p1c, m13 && p1d);
                aF[k2][0] = bpack(m00 && !p0a, m01 && !p0b);
                aF[k2][1] = bpack(m10 && !p1a, m11 && !p1b);
                aF[k2][2] = bpack(m02 && !p0c, m03 && !p0d);
                aF[k2][3] = bpack(m12 && !p1c, m13 && !p1d);
            }

#define MMA_TILE(NT, N0)                                                      \
            {                                                                 \
                const uint32_t ae = base + (uint32_t)(N0) * PB2 + bloff +     \
                                    (uint32_t)ga * 64;                        \
                uint32_t bE[4], bF[4];                                        \
                LDM4(bE[0], bE[1], bE[2], bE[3], ae);                         \
                LDM4(bF[0], bF[1], bF[2], bF[3], ae + TILE_B);                \
                mma_f16(accE[NT], aE[0][0], aE[0][1], aE[0][2], aE[0][3],     \
                        bE[0], bE[1]);                                        \
                mma_f16(accF[NT], aF[0][0], aF[0][1], aF[0][2], aF[0][3],     \
                        bF[0], bF[1]);                                        \
                mma_f16(accE[NT], aE[1][0], aE[1][1], aE[1][2], aE[1][3],     \
                        bE[2], bE[3]);                                        \
                mma_f16(accF[NT], aF[1][0], aF[1][1], aF[1][2], aF[1][3],     \
                        bF[2], bF[3]);                                        \
            }
#pragma unroll
            for (int nt = 0; nt < 8; nt++) MMA_TILE(nt, nbase + nt * 8);
            if (!wn) MMA_TILE(8, 64);
#undef MMA_TILE
        }
    }

    // ---- partial denominators (col 128 = wn1, nt7, elem 0/2) ----
    if (wn == 1 && tig == 0) {
        s_den[wm * 16 + g]     = E10 * accE[7][0] + F10 * accF[7][0];
        s_den[wm * 16 + g + 8] = E11 * accE[7][2] + F11 * accF[7][2];
    }
    __syncthreads();

    // ---- write partials to scratch ----
    float* gp = g_part[jh];
#pragma unroll
    for (int nt = 0; nt < 9; nt++) {
        if (wn == 1 && nt >= 7) break;
        const int cl = nbase + nt * 8 + 2 * tig;
        *(float2*)(gp + (size_t)gr0 * FOUT_ + cl) =
            make_float2(E10 * accE[nt][0] + F10 * accF[nt][0],
                        E10 * accE[nt][1] + F10 * accF[nt][1]);
        *(float2*)(gp + (size_t)gr1 * FOUT_ + cl) =
            make_float2(E11 * accE[nt][2] + F11 * accF[nt][2],
                        E11 * accE[nt][3] + F11 * accF[nt][3]);
    }
    if (t < 64) g_den[jh][b * N_ + i0 + t] = s_den[t];
    __threadfence();
    __syncthreads();
    if (t == 0) s_old = atomicAdd(&g_cnt[tile], 1);
    __syncthreads();

    if (s_old == 1) {
        __threadfence();   // acquire: other CTA's partials now visible
        const float* go = g_part[jh ^ 1];
        const float* gdo = g_den[jh ^ 1];
        const float inv0 = 1.0f / (s_den[wm * 16 + g] + gdo[gr0]);
        const float inv1 = 1.0f / (s_den[wm * 16 + g + 8] + gdo[gr1]);
#pragma unroll
        for (int nt = 0; nt < 9; nt++) {
            if (wn == 1 && nt >= 7) break;
            const int cl = nbase + nt * 8 + 2 * tig;
            float2 o0 = *(const float2*)(go + (size_t)gr0 * FOUT_ + cl);
            float2 o1 = *(const float2*)(go + (size_t)gr1 * FOUT_ + cl);
            *(float2*)(out + (size_t)gr0 * FOUT_ + cl) = make_float2(
                (E10 * accE[nt][0] + F10 * accF[nt][0] + o0.x) * inv0,
                (E10 * accE[nt][1] + F10 * accF[nt][1] + o0.y) * inv0);
            *(float2*)(out + (size_t)gr1 * FOUT_ + cl) = make_float2(
                (E11 * accE[nt][2] + F11 * accF[nt][2] + o1.x) * inv1,
                (E11 * accE[nt][3] + F11 * accF[nt][3] + o1.y) * inv1);
        }
        if (t == 0) g_cnt[tile] = 0;   // reset for next graph replay
    }
}

// ---------------------------------------------------------------------------
extern "C" void kernel_launch(void* const* d_in, const int* in_sizes, int n_in,
                              void* d_out, int out_size) {
    const float* X   = (const float*)d_in[0];
    const float* W   = (const float*)d_in[1];
    const float* a1  = (const float*)d_in[2];
    const float* a2  = (const float*)d_in[3];
    const int*   adj = (const int*)d_in[4];
    // d_in[5] = adj_tree: unused by the reference forward
    const int* d1p = (const int*)d_in[6];
    const int* d2p = (const int*)d_in[7];
    float* out = (float*)d_out;

    cudaFuncSetAttribute(k_gemm_tc, cudaFuncAttributeMaxDynamicSharedMemorySize, GSM);
    k_gemm_tc<<<ROWS_TOT / 64, 256, GSM>>>(X, W, a1, a2);

    cudaFuncSetAttribute(k_attn_tc, cudaFuncAttributeMaxDynamicSharedMemorySize, ASM);
    k_attn_tc<<<B_ * 32 * 2, 256, ASM>>>(adj, d1p, d2p, out);
}

// round 9
// speedup vs baseline: 1.2241x; 1.0064x over previous
#include <cuda_runtime.h>
#include <cuda_bf16.h>
#include <cuda_fp16.h>
#include <cstdint>

#define B_    4
#define N_    2048
#define FIN_  512
#define FOUT_ 128
#define ROWS_TOT (B_ * N_)
#define PX    144    // X tile pitch: 64 bf16 = 128B + 16 pad
#define PW    272    // W tile pitch: 128 bf16 = 256B + 16 pad
#define PB2   144    // attn B tile pitch
#define TROWS 136    // o-rows in hE/hF: 128 data + 1 sums + 7 zero pad
#define TILE_B (TROWS * PB2)   // 19584

// ---------------- global scratch (no cudaMalloc allowed) --------------------
__device__ __align__(16) __half g_hE[B_ * TROWS * N_];  // [b][o][j] E2[j]*h; row128=E2
__device__ __align__(16) __half g_hF[B_ * TROWS * N_];  // F2 variant
__device__ float g_t1[ROWS_TOT], g_t2[ROWS_TOT];
__device__ float g_E1[ROWS_TOT], g_F1[ROWS_TOT];
__device__ __align__(16) float g_part[2][ROWS_TOT * FOUT_];  // j-half partials
__device__ float g_den[2][ROWS_TOT];
__device__ int   g_cnt[B_ * 32];                              // per-i-tile arrival

// ---------------- helpers ----------------------------------------------------
__device__ __forceinline__ void mma_bf16(float* c,
    uint32_t a0, uint32_t a1, uint32_t a2, uint32_t a3, uint32_t b0, uint32_t b1) {
    asm volatile(
        "mma.sync.aligned.m16n8k16.row.col.f32.bf16.bf16.f32 "
        "{%0,%1,%2,%3},{%4,%5,%6,%7},{%8,%9},{%0,%1,%2,%3};"
        : "+f"(c[0]), "+f"(c[1]), "+f"(c[2]), "+f"(c[3])
        : "r"(a0), "r"(a1), "r"(a2), "r"(a3), "r"(b0), "r"(b1));
}
__device__ __forceinline__ void mma_f16(float* c,
    uint32_t a0, uint32_t a1, uint32_t a2, uint32_t a3, uint32_t b0, uint32_t b1) {
    asm volatile(
        "mma.sync.aligned.m16n8k16.row.col.f32.f16.f16.f32 "
        "{%0,%1,%2,%3},{%4,%5,%6,%7},{%8,%9},{%0,%1,%2,%3};"
        : "+f"(c[0]), "+f"(c[1]), "+f"(c[2]), "+f"(c[3])
        : "r"(a0), "r"(a1), "r"(a2), "r"(a3), "r"(b0), "r"(b1));
}
#define LDM4(r0, r1, r2, r3, a)                                          \
    asm volatile("ldmatrix.sync.aligned.m8n8.x4.shared.b16 "             \
                 "{%0,%1,%2,%3},[%4];"                                   \
                 : "=r"(r0), "=r"(r1), "=r"(r2), "=r"(r3) : "r"(a))
#define LDM4T(r0, r1, r2, r3, a)                                         \
    asm volatile("ldmatrix.sync.aligned.m8n8.x4.trans.shared.b16 "       \
                 "{%0,%1,%2,%3},[%4];"                                   \
                 : "=r"(r0), "=r"(r1), "=r"(r2), "=r"(r3) : "r"(a))
__device__ __forceinline__ uint32_t bf2u(__nv_bfloat162 v) {
    return *reinterpret_cast<uint32_t*>(&v);
}
__device__ __forceinline__ void split2(float a, float b, uint32_t& hi, uint32_t& lo) {
    __nv_bfloat162 h = __floats2bfloat162_rn(a, b);
    __nv_bfloat162 l = __floats2bfloat162_rn(a - __bfloat162float(h.x),
                                             b - __bfloat162float(h.y));
    hi = bf2u(h); lo = bf2u(l);
}
__device__ __forceinline__ uint32_t h2u(__half2 v) {
    return *reinterpret_cast<uint32_t*>(&v);
}
// expand 2-bit pair -> fp16x2 {0,1}
__device__ __forceinline__ uint32_t pexp(uint32_t p) {
    return ((p & 1) ? 0x3C00u : 0u) | ((p & 2) ? 0x3C000000u : 0u);
}
#define CPASYNC16(dst, src) \
    asm volatile("cp.async.cg.shared.global [%0], [%1], 16;" :: "r"(dst), "l"(src))
#define CPCOMMIT() asm volatile("cp.async.commit_group;" ::: "memory")
#define CPWAIT(n)  asm volatile("cp.async.wait_group %0;" :: "n"(n) : "memory")
__device__ __forceinline__ uint32_t smem_u32(const void* p) {
    uint32_t a;
    asm("{ .reg .u64 t; cvta.to.shared.u64 t, %1; cvt.u32.u64 %0, t; }"
        : "=r"(a) : "l"(p));
    return a;
}

// ---------------------------------------------------------------------------
// K1: h = X @ W (bf16 hi/lo 3-MMA), W split inline (R6/R8 version, verbatim).
// ---------------------------------------------------------------------------
#define GXH 0
#define GXL 9216
#define GWH 18432
#define GWL 35840
#define GA1 53248
#define GA2 53760
#define GE2 54272
#define GF2 54528
#define GSM 54784

__global__ __launch_bounds__(256) void k_gemm_tc(const float* __restrict__ X,
                                                 const float* __restrict__ W,
                                                 const float* __restrict__ a1,
                                                 const float* __restrict__ a2) {
    extern __shared__ char sm[];
    const uint32_t smb = smem_u32(sm);
    const int t = threadIdx.x, w = t >> 5, lane = t & 31;
    const int wm = w & 3, wn = w >> 2;
    const int row0 = blockIdx.x * 64;

    if (t < 128) {
        ((float*)(sm + GA1))[t] = a1[t];
        ((float*)(sm + GA2))[t] = a2[t];
    }

    float acc[8][4];
#pragma unroll
    for (int nt = 0; nt < 8; nt++)
        acc[nt][0] = acc[nt][1] = acc[nt][2] = acc[nt][3] = 0.f;

    const uint32_t ax_off =
        (uint32_t)(wm * 16 + ((lane >> 3) & 1) * 8 + (lane & 7)) * PX +
        (lane >> 4) * 16;
    const uint32_t wl_row = (uint32_t)lane * PW;

    for (int c = 0; c < 8; c++) {
        const int kc = c * 64;
#pragma unroll
        for (int l = 0; l < 4; l++) {
            int f = t + l * 256;
            int m = f >> 4, kq = (f & 15) * 4;
            float4 v = *(const float4*)(X + (size_t)(row0 + m) * FIN_ + kc + kq);
            uint32_t h0, l0, h1, l1;
            split2(v.x, v.y, h0, l0);
            split2(v.z, v.w, h1, l1);
            *(uint2*)(sm + GXH + m * PX + kq * 2) = make_uint2(h0, h1);
            *(uint2*)(sm + GXL + m * PX + kq * 2) = make_uint2(l0, l1);
        }
#pragma unroll
        for (int l = 0; l < 8; l++) {
            int f = t + l * 256;
            int k = f >> 5, nq = (f & 31) * 4;
            float4 v = *(const float4*)(W + (size_t)(kc + k) * FOUT_ + nq);
            uint32_t h0, l0, h1, l1;
            split2(v.x, v.y, h0, l0);
            split2(v.z, v.w, h1, l1);
            *(uint2*)(sm + GWH + k * PW + nq * 2) = make_uint2(h0, h1);
            *(uint2*)(sm + GWL + k * PW + nq * 2) = make_uint2(l0, l1);
        }
        __syncthreads();

        uint32_t ah[4][4], al[4][4];
#pragma unroll
        for (int ks = 0; ks < 4; ks++) {
            LDM4(ah[ks][0], ah[ks][1], ah[ks][2], ah[ks][3],
                 smb + GXH + ax_off + ks * 32);
            LDM4(al[ks][0], al[ks][1], al[ks][2], al[ks][3],
                 smb + GXL + ax_off + ks * 32);
        }
#pragma unroll
        for (int nt = 0; nt < 8; nt++) {
            const int n0 = wn * 64 + nt * 8;
            const uint32_t wadr = smb + GWH + wl_row + n0 * 2;
            uint32_t bh[8], bl[8];
            LDM4T(bh[0], bh[1], bh[2], bh[3], wadr);
            LDM4T(bh[4], bh[5], bh[6], bh[7], wadr + 32 * PW);
            LDM4T(bl[0], bl[1], bl[2], bl[3], wadr + (GWL - GWH));
            LDM4T(bl[4], bl[5], bl[6], bl[7], wadr + (GWL - GWH) + 32 * PW);
#pragma unroll
            for (int ks = 0; ks < 4; ks++) {
                mma_bf16(acc[nt], ah[ks][0], ah[ks][1], ah[ks][2], ah[ks][3],
                         bh[2 * ks], bh[2 * ks + 1]);
                mma_bf16(acc[nt], ah[ks][0], ah[ks][1], ah[ks][2], ah[ks][3],
                         bl[2 * ks], bl[2 * ks + 1]);
                mma_bf16(acc[nt], al[ks][0], al[ks][1], al[ks][2], al[ks][3],
                         bh[2 * ks], bh[2 * ks + 1]);
            }
        }
        __syncthreads();
    }

    // ---- epilogue ----
    const int g = lane >> 2, tig = lane & 3;
    float* Ds = (float*)sm;
    {
        const int r = wm * 16 + g, cl = wn * 64 + 2 * tig;
#pragma unroll
        for (int nt = 0; nt < 8; nt++) {
            Ds[r * 132 + cl + nt * 8]           = acc[nt][0];
            Ds[r * 132 + cl + nt * 8 + 1]       = acc[nt][1];
            Ds[(r + 8) * 132 + cl + nt * 8]     = acc[nt][2];
            Ds[(r + 8) * 132 + cl + nt * 8 + 1] = acc[nt][3];
        }
    }
    __syncthreads();
    const float* A1 = (const float*)(sm + GA1);
    const float* A2 = (const float*)(sm + GA2);
    float* E2s = (float*)(sm + GE2);
    float* F2s = (float*)(sm + GF2);
#pragma unroll
    for (int rr = 0; rr < 8; rr++) {
        int r = w * 8 + rr;
        float s1 = 0.f, s2 = 0.f;
#pragma unroll
        for (int q = 0; q < 4; q++) {
            float v = Ds[r * 132 + lane + 32 * q];
            s1 = fmaf(v, A1[lane + 32 * q], s1);
            s2 = fmaf(v, A2[lane + 32 * q], s2);
        }
#pragma unroll
        for (int o = 16; o; o >>= 1) {
            s1 += __shfl_down_sync(0xffffffffu, s1, o);
            s2 += __shfl_down_sync(0xffffffffu, s2, o);
        }
        if (lane == 0) {
            int gr = row0 + r;
            g_t1[gr] = s1;  g_t2[gr] = s2;
            g_E1[gr] = expf(s1);          g_F1[gr] = expf(0.2f * s1);
            E2s[r] = expf(s2);            F2s[r] = expf(0.2f * s2);
        }
    }
    __syncthreads();
    {
        const int o = t & 127, half = t >> 7;
        const int bb = row0 >> 11, j0g = row0 & (N_ - 1);
        uint32_t uE[16], uF[16];
#pragma unroll
        for (int ii = 0; ii < 16; ii++) {
            int j0l = half * 32 + 2 * ii;
            float v0 = Ds[j0l * 132 + o], v1 = Ds[(j0l + 1) * 132 + o];
            uE[ii] = h2u(__floats2half2_rn(v0 * E2s[j0l], v1 * E2s[j0l + 1]));
            uF[ii] = h2u(__floats2half2_rn(v0 * F2s[j0l], v1 * F2s[j0l + 1]));
        }
        size_t base = ((size_t)(bb * TROWS) + o) * N_ + j0g + half * 32;
#pragma unroll
        for (int q = 0; q < 4; q++) {
            *(uint4*)(g_hE + base + q * 8) =
                make_uint4(uE[4 * q], uE[4 * q + 1], uE[4 * q + 2], uE[4 * q + 3]);
            *(uint4*)(g_hF + base + q * 8) =
                make_uint4(uF[4 * q], uF[4 * q + 1], uF[4 * q + 2], uF[4 * q + 3]);
        }
        if (t < 64) {
            size_t sbase = ((size_t)(bb * TROWS) + 128) * N_ + j0g + t;
            g_hE[sbase] = __float2half_rn(E2s[t]);
            g_hF[sbase] = __float2half_rn(F2s[t]);
        }
    }
}

// ---------------------------------------------------------------------------
// K2: attention, j-split x2 + in-kernel combine + BIT-MASK PREFILL.
// Phase 1: stream adj slice once, ballot mask bits into smem (16 KB).
// Phase 2: 16-chunk mainloop; A-frags from LDS.64 bit extraction; no T2/adj.
// ---------------------------------------------------------------------------
#define MES  (4 * TILE_B)           // 78336: maskE bits, 64 rows x 34 u32
#define MFS  (MES + 64 * 34 * 4)    // 87040: maskF bits
#define ASM  (MFS + 64 * 34 * 4)    // 95744 total dynamic

__global__ __launch_bounds__(256, 2) void k_attn_tc(const int* __restrict__ adj,
                                                    const int* __restrict__ d1p,
                                                    const int* __restrict__ d2p,
                                                    float* __restrict__ out) {
    extern __shared__ char sm[];
    __shared__ float s_den[64];
    __shared__ int s_old;
    const uint32_t smb = smem_u32(sm);
    const int t = threadIdx.x, w = t >> 5, lane = t & 31;
    const int g = lane >> 2, tig = lane & 3;
    const int wm = w & 3, wn = w >> 2;
    const int tile = blockIdx.x >> 1, jh = blockIdx.x & 1;
    const int b = tile >> 5, i0 = (tile & 31) * 64;
    const int jbase = jh * 1024;
    const int d1 = *d1p, d2 = *d2p;

    const __half* gEb = g_hE + (size_t)b * TROWS * N_;
    const __half* gFb = g_hF + (size_t)b * TROWS * N_;

    // cp.async loader for B tiles (same as R8)
    auto load_chunk = [&](int j0, int buf) {
#pragma unroll
        for (int l = 0; l < 9; l++) {
            int f = t + l * 256;
            if (f < 2176) {
                int mat = f >= 1088;
                int idx = f - (mat ? 1088 : 0);
                int row = idx >> 3, u = idx & 7;
                const __half* src = (mat ? gFb : gEb) + (size_t)row * N_ + j0 + u * 8;
                uint32_t dst = smb + buf * (2 * TILE_B) + mat * TILE_B + row * PB2 + u * 16;
                CPASYNC16(dst, src);
            }
        }
    };

    // issue first B chunk, then overlap prefill with its DMA
    load_chunk(jbase, 0);
    CPCOMMIT();

    // ---- PREFILL: adj slice -> bit masks in smem ----
    {
        uint32_t* ME = (uint32_t*)(sm + MES);
        uint32_t* MF = (uint32_t*)(sm + MFS);
        const float* t2p = g_t2 + b * N_ + jbase;
#pragma unroll 1
        for (int rr = 0; rr < 8; rr++) {
            const int lr = w * 8 + rr;
            const float nt1 = -g_t1[b * N_ + i0 + lr];
            const int* arow = adj + (size_t)(b * N_ + i0 + lr) * N_ + jbase;
#pragma unroll 1
            for (int b8 = 0; b8 < 4; b8++) {
                int av[8]; float tv[8];
#pragma unroll
                for (int k = 0; k < 8; k++) {
                    av[k] = arow[(b8 * 8 + k) * 32 + lane];
                    tv[k] = t2p[(b8 * 8 + k) * 32 + lane];
                }
#pragma unroll
                for (int k = 0; k < 8; k++) {
                    bool m = (av[k] == d1) | (av[k] == d2);
                    bool p = tv[k] > nt1;
                    uint32_t bE = __ballot_sync(0xffffffffu, m & p);
                    uint32_t bF = __ballot_sync(0xffffffffu, m & (!p));
                    if (lane == 0) {
                        ME[lr * 34 + b8 * 8 + k] = bE;
                        MF[lr * 34 + b8 * 8 + k] = bF;
                    }
                }
            }
        }
    }

    const int r0 = i0 + wm * 16 + g, r1 = r0 + 8;
    const int lr0 = wm * 16 + g, lr1 = lr0 + 8;
    const int gr0 = b * N_ + r0, gr1 = b * N_ + r1;
    const float E10 = g_E1[gr0], F10 = g_F1[gr0];
    const float E11 = g_E1[gr1], F11 = g_F1[gr1];

    float accE[9][4], accF[9][4];
#pragma unroll
    for (int nt = 0; nt < 9; nt++)
#pragma unroll
        for (int q = 0; q < 4; q++) { accE[nt][q] = 0.f; accF[nt][q] = 0.f; }

    const int nbase = wn ? 72 : 0;
    const uint32_t bloff = (uint32_t)(lane & 7) * PB2 + (lane >> 3) * 16;
    const uint64_t* ME64 = (const uint64_t*)(sm + MES);
    const uint64_t* MF64 = (const uint64_t*)(sm + MFS);

    for (int c = 0; c < 16; c++) {
        const int buf = c & 1;
        __syncthreads();
        if (c + 1 < 16) {
            load_chunk(jbase + (c + 1) * 64, buf ^ 1);
            CPCOMMIT();
            CPWAIT(1);
        } else {
            CPWAIT(0);
        }
        __syncthreads();

        const uint32_t base = smb + buf * (2 * TILE_B);
        const uint64_t mE0 = ME64[lr0 * 17 + c], mE1 = ME64[lr1 * 17 + c];
        const uint64_t mF0 = MF64[lr0 * 17 + c], mF1 = MF64[lr1 * 17 + c];

#pragma unroll
        for (int ga = 0; ga < 2; ga++) {
            uint32_t aE[2][4], aF[2][4];
#pragma unroll
            for (int k2 = 0; k2 < 2; k2++) {
                const int s = 16 * (ga * 2 + k2) + 2 * tig;
                aE[k2][0] = pexp((uint32_t)(mE0 >> s) & 3);
                aE[k2][1] = pexp((uint32_t)(mE1 >> s) & 3);
                aE[k2][2] = pexp((uint32_t)(mE0 >> (s + 8)) & 3);
                aE[k2][3] = pexp((uint32_t)(mE1 >> (s + 8)) & 3);
                aF[k2][0] = pexp((uint32_t)(mF0 >> s) & 3);
                aF[k2][1] = pexp((uint32_t)(mF1 >> s) & 3);
                aF[k2][2] = pexp((uint32_t)(mF0 >> (s + 8)) & 3);
                aF[k2][3] = pexp((uint32_t)(mF1 >> (s + 8)) & 3);
            }

#define MMA_TILE(NT, N0)                                                      \
            {                                                                 \
                const uint32_t ae = base + (uint32_t)(N0) * PB2 + bloff +     \
                                    (uint32_t)ga * 64;                        \
                uint32_t bE[4], bF[4];                                        \
                LDM4(bE[0], bE[1], bE[2], bE[3], ae);                         \
                LDM4(bF[0], bF[1], bF[2], bF[3], ae + TILE_B);                \
                mma_f16(accE[NT], aE[0][0], aE[0][1], aE[0][2], aE[0][3],     \
                        bE[0], bE[1]);                                        \
                mma_f16(accF[NT], aF[0][0], aF[0][1], aF[0][2], aF[0][3],     \
                        bF[0], bF[1]);                                        \
                mma_f16(accE[NT], aE[1][0], aE[1][1], aE[1][2], aE[1][3],     \
                        bE[2], bE[3]);                                        \
                mma_f16(accF[NT], aF[1][0], aF[1][1], aF[1][2], aF[1][3],     \
                        bF[2], bF[3]);                                        \
            }
#pragma unroll
            for (int nt = 0; nt < 8; nt++) MMA_TILE(nt, nbase + nt * 8);
            if (!wn) MMA_TILE(8, 64);
#undef MMA_TILE
        }
    }

    // ---- partial denominators (col 128 = wn1, nt7, elem 0/2) ----
    if (wn == 1 && tig == 0) {
        s_den[wm * 16 + g]     = E10 * accE[7][0] + F10 * accF[7][0];
        s_den[wm * 16 + g + 8] = E11 * accE[7][2] + F11 * accF[7][2];
    }
    __syncthreads();

    // ---- write partials to scratch ----
    float* gp = g_part[jh];
#pragma unroll
    for (int nt = 0; nt < 9; nt++) {
        if (wn == 1 && nt >= 7) break;
        const int cl = nbase + nt * 8 + 2 * tig;
        *(float2*)(gp + (size_t)gr0 * FOUT_ + cl) =
            make_float2(E10 * accE[nt][0] + F10 * accF[nt][0],
                        E10 * accE[nt][1] + F10 * accF[nt][1]);
        *(float2*)(gp + (size_t)gr1 * FOUT_ + cl) =
            make_float2(E11 * accE[nt][2] + F11 * accF[nt][2],
                        E11 * accE[nt][3] + F11 * accF[nt][3]);
    }
    if (t < 64) g_den[jh][b * N_ + i0 + t] = s_den[t];
    __threadfence();
    __syncthreads();
    if (t == 0) s_old = atomicAdd(&g_cnt[tile], 1);
    __syncthreads();

    if (s_old == 1) {
        __threadfence();   // acquire: other CTA's partials now visible
        const float* go = g_part[jh ^ 1];
        const float* gdo = g_den[jh ^ 1];
        const float inv0 = 1.0f / (s_den[wm * 16 + g] + gdo[gr0]);
        const float inv1 = 1.0f / (s_den[wm * 16 + g + 8] + gdo[gr1]);
#pragma unroll
        for (int nt = 0; nt < 9; nt++) {
            if (wn == 1 && nt >= 7) break;
            const int cl = nbase + nt * 8 + 2 * tig;
            float2 o0 = *(const float2*)(go + (size_t)gr0 * FOUT_ + cl);
            float2 o1 = *(const float2*)(go + (size_t)gr1 * FOUT_ + cl);
            *(float2*)(out + (size_t)gr0 * FOUT_ + cl) = make_float2(
                (E10 * accE[nt][0] + F10 * accF[nt][0] + o0.x) * inv0,
                (E10 * accE[nt][1] + F10 * accF[nt][1] + o0.y) * inv0);
            *(float2*)(out + (size_t)gr1 * FOUT_ + cl) = make_float2(
                (E11 * accE[nt][2] + F11 * accF[nt][2] + o1.x) * inv1,
                (E11 * accE[nt][3] + F11 * accF[nt][3] + o1.y) * inv1);
        }
        if (t == 0) g_cnt[tile] = 0;   // reset for next graph replay
    }
}

// ---------------------------------------------------------------------------
extern "C" void kernel_launch(void* const* d_in, const int* in_sizes, int n_in,
                              void* d_out, int out_size) {
    const float* X   = (const float*)d_in[0];
    const float* W   = (const float*)d_in[1];
    const float* a1  = (const float*)d_in[2];
    const float* a2  = (const float*)d_in[3];
    const int*   adj = (const int*)d_in[4];
    // d_in[5] = adj_tree: unused by the reference forward
    const int* d1p = (const int*)d_in[6];
    const int* d2p = (const int*)d_in[7];
    float* out = (float*)d_out;

    cudaFuncSetAttribute(k_gemm_tc, cudaFuncAttributeMaxDynamicSharedMemorySize, GSM);
    k_gemm_tc<<<ROWS_TOT / 64, 256, GSM>>>(X, W, a1, a2);

    cudaFuncSetAttribute(k_attn_tc, cudaFuncAttributeMaxDynamicSharedMemorySize, ASM);
    k_attn_tc<<<B_ * 32 * 2, 256, ASM>>>(adj, d1p, d2p, out);
}

// round 10
// speedup vs baseline: 1.2272x; 1.0026x over previous
#include <cuda_runtime.h>
#include <cuda_bf16.h>
#include <cuda_fp16.h>
#include <cstdint>

#define B_    4
#define N_    2048
#define FIN_  512
#define FOUT_ 128
#define ROWS_TOT (B_ * N_)
#define PX    144    // X tile pitch: 64 bf16 = 128B + 16 pad
#define PW    272    // W tile pitch: 128 bf16 = 256B + 16 pad
#define PB2   144    // attn B tile pitch
#define TROWS 136    // o-rows in hE/hF: 128 data + 1 sums + 7 zero pad
#define TILE_B (TROWS * PB2)   // 19584

// ---------------- global scratch (no cudaMalloc allowed) --------------------
__device__ __align__(16) __half g_hE[B_ * TROWS * N_];  // [b][o][j] E2[j]*h; row128=E2
__device__ __align__(16) __half g_hF[B_ * TROWS * N_];  // F2 variant
__device__ float g_t1[ROWS_TOT], g_t2[ROWS_TOT];
__device__ float g_E1[ROWS_TOT], g_F1[ROWS_TOT];
__device__ __align__(16) float g_part[2][ROWS_TOT * FOUT_];  // j-half partials
__device__ float g_den[2][ROWS_TOT];
__device__ int   g_cnt[B_ * 32];                              // per-i-tile arrival

// ---------------- helpers ----------------------------------------------------
__device__ __forceinline__ void mma_bf16(float* c,
    uint32_t a0, uint32_t a1, uint32_t a2, uint32_t a3, uint32_t b0, uint32_t b1) {
    asm volatile(
        "mma.sync.aligned.m16n8k16.row.col.f32.bf16.bf16.f32 "
        "{%0,%1,%2,%3},{%4,%5,%6,%7},{%8,%9},{%0,%1,%2,%3};"
        : "+f"(c[0]), "+f"(c[1]), "+f"(c[2]), "+f"(c[3])
        : "r"(a0), "r"(a1), "r"(a2), "r"(a3), "r"(b0), "r"(b1));
}
__device__ __forceinline__ void mma_f16(float* c,
    uint32_t a0, uint32_t a1, uint32_t a2, uint32_t a3, uint32_t b0, uint32_t b1) {
    asm volatile(
        "mma.sync.aligned.m16n8k16.row.col.f32.f16.f16.f32 "
        "{%0,%1,%2,%3},{%4,%5,%6,%7},{%8,%9},{%0,%1,%2,%3};"
        : "+f"(c[0]), "+f"(c[1]), "+f"(c[2]), "+f"(c[3])
        : "r"(a0), "r"(a1), "r"(a2), "r"(a3), "r"(b0), "r"(b1));
}
#define LDM4(r0, r1, r2, r3, a)                                          \
    asm volatile("ldmatrix.sync.aligned.m8n8.x4.shared.b16 "             \
                 "{%0,%1,%2,%3},[%4];"                                   \
                 : "=r"(r0), "=r"(r1), "=r"(r2), "=r"(r3) : "r"(a))
#define LDM4T(r0, r1, r2, r3, a)                                         \
    asm volatile("ldmatrix.sync.aligned.m8n8.x4.trans.shared.b16 "       \
                 "{%0,%1,%2,%3},[%4];"                                   \
                 : "=r"(r0), "=r"(r1), "=r"(r2), "=r"(r3) : "r"(a))
__device__ __forceinline__ uint32_t bf2u(__nv_bfloat162 v) {
    return *reinterpret_cast<uint32_t*>(&v);
}
__device__ __forceinline__ void split2(float a, float b, uint32_t& hi, uint32_t& lo) {
    __nv_bfloat162 h = __floats2bfloat162_rn(a, b);
    __nv_bfloat162 l = __floats2bfloat162_rn(a - __bfloat162float(h.x),
                                             b - __bfloat162float(h.y));
    hi = bf2u(h); lo = bf2u(l);
}
__device__ __forceinline__ uint32_t h2u(__half2 v) {
    return *reinterpret_cast<uint32_t*>(&v);
}
// expand 2-bit pair -> fp16x2 {0,1}
__device__ __forceinline__ uint32_t pexp(uint32_t p) {
    return ((p & 1) ? 0x3C00u : 0u) | ((p & 2) ? 0x3C000000u : 0u);
}
#define CPASYNC16(dst, src) \
    asm volatile("cp.async.cg.shared.global [%0], [%1], 16;" :: "r"(dst), "l"(src))
#define CPCOMMIT() asm volatile("cp.async.commit_group;" ::: "memory")
#define CPWAIT(n)  asm volatile("cp.async.wait_group %0;" :: "n"(n) : "memory")
__device__ __forceinline__ uint32_t smem_u32(const void* p) {
    uint32_t a;
    asm("{ .reg .u64 t; cvta.to.shared.u64 t, %1; cvt.u32.u64 %0, t; }"
        : "=r"(a) : "l"(p));
    return a;
}

// ---------------------------------------------------------------------------
// K1: h = X @ W (bf16 hi/lo 3-MMA), W split inline (R6/R8 version, verbatim).
// ---------------------------------------------------------------------------
#define GXH 0
#define GXL 9216
#define GWH 18432
#define GWL 35840
#define GA1 53248
#define GA2 53760
#define GE2 54272
#define GF2 54528
#define GSM 54784

__global__ __launch_bounds__(256) void k_gemm_tc(const float* __restrict__ X,
                                                 const float* __restrict__ W,
                                                 const float* __restrict__ a1,
                                                 const float* __restrict__ a2) {
    extern __shared__ char sm[];
    const uint32_t smb = smem_u32(sm);
    const int t = threadIdx.x, w = t >> 5, lane = t & 31;
    const int wm = w & 3, wn = w >> 2;
    const int row0 = blockIdx.x * 64;

    if (t < 128) {
        ((float*)(sm + GA1))[t] = a1[t];
        ((float*)(sm + GA2))[t] = a2[t];
    }

    float acc[8][4];
#pragma unroll
    for (int nt = 0; nt < 8; nt++)
        acc[nt][0] = acc[nt][1] = acc[nt][2] = acc[nt][3] = 0.f;

    const uint32_t ax_off =
        (uint32_t)(wm * 16 + ((lane >> 3) & 1) * 8 + (lane & 7)) * PX +
        (lane >> 4) * 16;
    const uint32_t wl_row = (uint32_t)lane * PW;

    for (int c = 0; c < 8; c++) {
        const int kc = c * 64;
#pragma unroll
        for (int l = 0; l < 4; l++) {
            int f = t + l * 256;
            int m = f >> 4, kq = (f & 15) * 4;
            float4 v = *(const float4*)(X + (size_t)(row0 + m) * FIN_ + kc + kq);
            uint32_t h0, l0, h1, l1;
            split2(v.x, v.y, h0, l0);
            split2(v.z, v.w, h1, l1);
            *(uint2*)(sm + GXH + m * PX + kq * 2) = make_uint2(h0, h1);
            *(uint2*)(sm + GXL + m * PX + kq * 2) = make_uint2(l0, l1);
        }
#pragma unroll
        for (int l = 0; l < 8; l++) {
            int f = t + l * 256;
            int k = f >> 5, nq = (f & 31) * 4;
            float4 v = *(const float4*)(W + (size_t)(kc + k) * FOUT_ + nq);
            uint32_t h0, l0, h1, l1;
            split2(v.x, v.y, h0, l0);
            split2(v.z, v.w, h1, l1);
            *(uint2*)(sm + GWH + k * PW + nq * 2) = make_uint2(h0, h1);
            *(uint2*)(sm + GWL + k * PW + nq * 2) = make_uint2(l0, l1);
        }
        __syncthreads();

        uint32_t ah[4][4], al[4][4];
#pragma unroll
        for (int ks = 0; ks < 4; ks++) {
            LDM4(ah[ks][0], ah[ks][1], ah[ks][2], ah[ks][3],
                 smb + GXH + ax_off + ks * 32);
            LDM4(al[ks][0], al[ks][1], al[ks][2], al[ks][3],
                 smb + GXL + ax_off + ks * 32);
        }
#pragma unroll
        for (int nt = 0; nt < 8; nt++) {
            const int n0 = wn * 64 + nt * 8;
            const uint32_t wadr = smb + GWH + wl_row + n0 * 2;
            uint32_t bh[8], bl[8];
            LDM4T(bh[0], bh[1], bh[2], bh[3], wadr);
            LDM4T(bh[4], bh[5], bh[6], bh[7], wadr + 32 * PW);
            LDM4T(bl[0], bl[1], bl[2], bl[3], wadr + (GWL - GWH));
            LDM4T(bl[4], bl[5], bl[6], bl[7], wadr + (GWL - GWH) + 32 * PW);
#pragma unroll
            for (int ks = 0; ks < 4; ks++) {
                mma_bf16(acc[nt], ah[ks][0], ah[ks][1], ah[ks][2], ah[ks][3],
                         bh[2 * ks], bh[2 * ks + 1]);
                mma_bf16(acc[nt], ah[ks][0], ah[ks][1], ah[ks][2], ah[ks][3],
                         bl[2 * ks], bl[2 * ks + 1]);
                mma_bf16(acc[nt], al[ks][0], al[ks][1], al[ks][2], al[ks][3],
                         bh[2 * ks], bh[2 * ks + 1]);
            }
        }
        __syncthreads();
    }

    // ---- epilogue ----
    const int g = lane >> 2, tig = lane & 3;
    float* Ds = (float*)sm;
    {
        const int r = wm * 16 + g, cl = wn * 64 + 2 * tig;
#pragma unroll
        for (int nt = 0; nt < 8; nt++) {
            Ds[r * 132 + cl + nt * 8]           = acc[nt][0];
            Ds[r * 132 + cl + nt * 8 + 1]       = acc[nt][1];
            Ds[(r + 8) * 132 + cl + nt * 8]     = acc[nt][2];
            Ds[(r + 8) * 132 + cl + nt * 8 + 1] = acc[nt][3];
        }
    }
    __syncthreads();
    const float* A1 = (const float*)(sm + GA1);
    const float* A2 = (const float*)(sm + GA2);
    float* E2s = (float*)(sm + GE2);
    float* F2s = (float*)(sm + GF2);
#pragma unroll
    for (int rr = 0; rr < 8; rr++) {
        int r = w * 8 + rr;
        float s1 = 0.f, s2 = 0.f;
#pragma unroll
        for (int q = 0; q < 4; q++) {
            float v = Ds[r * 132 + lane + 32 * q];
            s1 = fmaf(v, A1[lane + 32 * q], s1);
            s2 = fmaf(v, A2[lane + 32 * q], s2);
        }
#pragma unroll
        for (int o = 16; o; o >>= 1) {
            s1 += __shfl_down_sync(0xffffffffu, s1, o);
            s2 += __shfl_down_sync(0xffffffffu, s2, o);
        }
        if (lane == 0) {
            int gr = row0 + r;
            g_t1[gr] = s1;  g_t2[gr] = s2;
            g_E1[gr] = expf(s1);          g_F1[gr] = expf(0.2f * s1);
            E2s[r] = expf(s2);            F2s[r] = expf(0.2f * s2);
        }
    }
    __syncthreads();
    {
        const int o = t & 127, half = t >> 7;
        const int bb = row0 >> 11, j0g = row0 & (N_ - 1);
        uint32_t uE[16], uF[16];
#pragma unroll
        for (int ii = 0; ii < 16; ii++) {
            int j0l = half * 32 + 2 * ii;
            float v0 = Ds[j0l * 132 + o], v1 = Ds[(j0l + 1) * 132 + o];
            uE[ii] = h2u(__floats2half2_rn(v0 * E2s[j0l], v1 * E2s[j0l + 1]));
            uF[ii] = h2u(__floats2half2_rn(v0 * F2s[j0l], v1 * F2s[j0l + 1]));
        }
        size_t base = ((size_t)(bb * TROWS) + o) * N_ + j0g + half * 32;
#pragma unroll
        for (int q = 0; q < 4; q++) {
            *(uint4*)(g_hE + base + q * 8) =
                make_uint4(uE[4 * q], uE[4 * q + 1], uE[4 * q + 2], uE[4 * q + 3]);
            *(uint4*)(g_hF + base + q * 8) =
                make_uint4(uF[4 * q], uF[4 * q + 1], uF[4 * q + 2], uF[4 * q + 3]);
        }
        if (t < 64) {
            size_t sbase = ((size_t)(bb * TROWS) + 128) * N_ + j0g + t;
            g_hE[sbase] = __float2half_rn(E2s[t]);
            g_hF[sbase] = __float2half_rn(F2s[t]);
        }
    }
}

// ---------------------------------------------------------------------------
// K2: attention, j-split x2 + bit-mask prefill + PIPELINED mainloop:
//   - single __syncthreads per chunk
//   - B-fragment ldmatrix double-buffered one n-tile ahead of the MMA stream
// ---------------------------------------------------------------------------
#define MES  (4 * TILE_B)           // 78336: maskE bits, 64 rows x 34 u32
#define MFS  (MES + 64 * 34 * 4)    // 87040: maskF bits
#define ASM  (MFS + 64 * 34 * 4)    // 95744 total dynamic

__global__ __launch_bounds__(256, 2) void k_attn_tc(const int* __restrict__ adj,
                                                    const int* __restrict__ d1p,
                                                    const int* __restrict__ d2p,
                                                    float* __restrict__ out) {
    extern __shared__ char sm[];
    __shared__ float s_den[64];
    __shared__ int s_old;
    const uint32_t smb = smem_u32(sm);
    const int t = threadIdx.x, w = t >> 5, lane = t & 31;
    const int g = lane >> 2, tig = lane & 3;
    const int wm = w & 3, wn = w >> 2;
    const int tile = blockIdx.x >> 1, jh = blockIdx.x & 1;
    const int b = tile >> 5, i0 = (tile & 31) * 64;
    const int jbase = jh * 1024;
    const int d1 = *d1p, d2 = *d2p;

    const __half* gEb = g_hE + (size_t)b * TROWS * N_;
    const __half* gFb = g_hF + (size_t)b * TROWS * N_;

    auto load_chunk = [&](int j0, int buf) {
#pragma unroll
        for (int l = 0; l < 9; l++) {
            int f = t + l * 256;
            if (f < 2176) {
                int mat = f >= 1088;
                int idx = f - (mat ? 1088 : 0);
                int row = idx >> 3, u = idx & 7;
                const __half* src = (mat ? gFb : gEb) + (size_t)row * N_ + j0 + u * 8;
                uint32_t dst = smb + buf * (2 * TILE_B) + mat * TILE_B + row * PB2 + u * 16;
                CPASYNC16(dst, src);
            }
        }
    };

    // issue first B chunk, overlap prefill with its DMA
    load_chunk(jbase, 0);
    CPCOMMIT();

    // ---- PREFILL: adj slice -> bit masks in smem ----
    {
        uint32_t* ME = (uint32_t*)(sm + MES);
        uint32_t* MF = (uint32_t*)(sm + MFS);
        const float* t2p = g_t2 + b * N_ + jbase;
#pragma unroll 1
        for (int rr = 0; rr < 8; rr++) {
            const int lr = w * 8 + rr;
            const float nt1 = -g_t1[b * N_ + i0 + lr];
            const int* arow = adj + (size_t)(b * N_ + i0 + lr) * N_ + jbase;
#pragma unroll 1
            for (int b8 = 0; b8 < 4; b8++) {
                int av[8]; float tv[8];
#pragma unroll
                for (int k = 0; k < 8; k++) {
                    av[k] = arow[(b8 * 8 + k) * 32 + lane];
                    tv[k] = t2p[(b8 * 8 + k) * 32 + lane];
                }
#pragma unroll
                for (int k = 0; k < 8; k++) {
                    bool m = (av[k] == d1) | (av[k] == d2);
                    bool p = tv[k] > nt1;
                    uint32_t bE = __ballot_sync(0xffffffffu, m & p);
                    uint32_t bF = __ballot_sync(0xffffffffu, m & (!p));
                    if (lane == 0) {
                        ME[lr * 34 + b8 * 8 + k] = bE;
                        MF[lr * 34 + b8 * 8 + k] = bF;
                    }
                }
            }
        }
    }

    const int r0 = i0 + wm * 16 + g, r1 = r0 + 8;
    const int lr0 = wm * 16 + g, lr1 = lr0 + 8;
    const int gr0 = b * N_ + r0, gr1 = b * N_ + r1;
    const float E10 = g_E1[gr0], F10 = g_F1[gr0];
    const float E11 = g_E1[gr1], F11 = g_F1[gr1];

    float accE[9][4], accF[9][4];
#pragma unroll
    for (int nt = 0; nt < 9; nt++)
#pragma unroll
        for (int q = 0; q < 4; q++) { accE[nt][q] = 0.f; accF[nt][q] = 0.f; }

    const int nbase = wn ? 72 : 0;
    const uint32_t bloff = (uint32_t)(lane & 7) * PB2 + (lane >> 3) * 16;
    const uint64_t* ME64 = (const uint64_t*)(sm + MES);
    const uint64_t* MF64 = (const uint64_t*)(sm + MFS);

    for (int c = 0; c < 16; c++) {
        const int buf = c & 1;
        CPWAIT(0);            // chunk c landed (this thread's group)
        __syncthreads();      // c visible to all; buf^1 drained by all
        if (c + 1 < 16) {
            load_chunk(jbase + (c + 1) * 64, buf ^ 1);
            CPCOMMIT();
        }

        const uint32_t base = smb + buf * (2 * TILE_B);
        const uint64_t mE0 = ME64[lr0 * 17 + c], mE1 = ME64[lr1 * 17 + c];
        const uint64_t mF0 = MF64[lr0 * 17 + c], mF1 = MF64[lr1 * 17 + c];

#pragma unroll
        for (int ga = 0; ga < 2; ga++) {
            uint32_t aE[2][4], aF[2][4];
#pragma unroll
            for (int k2 = 0; k2 < 2; k2++) {
                const int s = 16 * (ga * 2 + k2) + 2 * tig;
                aE[k2][0] = pexp((uint32_t)(mE0 >> s) & 3);
                aE[k2][1] = pexp((uint32_t)(mE1 >> s) & 3);
                aE[k2][2] = pexp((uint32_t)(mE0 >> (s + 8)) & 3);
                aE[k2][3] = pexp((uint32_t)(mE1 >> (s + 8)) & 3);
                aF[k2][0] = pexp((uint32_t)(mF0 >> s) & 3);
                aF[k2][1] = pexp((uint32_t)(mF1 >> s) & 3);
                aF[k2][2] = pexp((uint32_t)(mF0 >> (s + 8)) & 3);
                aF[k2][3] = pexp((uint32_t)(mF1 >> (s + 8)) & 3);
            }

            // ---- pipelined B-frag loads + MMA ----
            const uint32_t abase = base + bloff + (uint32_t)ga * 64;
            uint32_t bE[2][4], bF[2][4];
            {
                const uint32_t ae = abase + (uint32_t)nbase * PB2;
                LDM4(bE[0][0], bE[0][1], bE[0][2], bE[0][3], ae);
                LDM4(bF[0][0], bF[0][1], bF[0][2], bF[0][3], ae + TILE_B);
            }
#pragma unroll
            for (int nt = 0; nt < 9; nt++) {
                const int cur = nt & 1, nxt = cur ^ 1;
                if (nt < 8) {
                    const uint32_t ae = abase + (uint32_t)(nbase + (nt + 1) * 8) * PB2;
                    LDM4(bE[nxt][0], bE[nxt][1], bE[nxt][2], bE[nxt][3], ae);
                    LDM4(bF[nxt][0], bF[nxt][1], bF[nxt][2], bF[nxt][3], ae + TILE_B);
                }
                if (nt < 8 || !wn) {
                    mma_f16(accE[nt], aE[0][0], aE[0][1], aE[0][2], aE[0][3],
                            bE[cur][0], bE[cur][1]);
                    mma_f16(accF[nt], aF[0][0], aF[0][1], aF[0][2], aF[0][3],
                            bF[cur][0], bF[cur][1]);
                    mma_f16(accE[nt], aE[1][0], aE[1][1], aE[1][2], aE[1][3],
                            bE[cur][2], bE[cur][3]);
                    mma_f16(accF[nt], aF[1][0], aF[1][1], aF[1][2], aF[1][3],
                            bF[cur][2], bF[cur][3]);
                }
            }
        }
    }

    // ---- partial denominators (col 128 = wn1, nt7, elem 0/2) ----
    if (wn == 1 && tig == 0) {
        s_den[wm * 16 + g]     = E10 * accE[7][0] + F10 * accF[7][0];
        s_den[wm * 16 + g + 8] = E11 * accE[7][2] + F11 * accF[7][2];
    }
    __syncthreads();

    // ---- write partials to scratch ----
    float* gp = g_part[jh];
#pragma unroll
    for (int nt = 0; nt < 9; nt++) {
        if (wn == 1 && nt >= 7) break;
        const int cl = nbase + nt * 8 + 2 * tig;
        *(float2*)(gp + (size_t)gr0 * FOUT_ + cl) =
            make_float2(E10 * accE[nt][0] + F10 * accF[nt][0],
                        E10 * accE[nt][1] + F10 * accF[nt][1]);
        *(float2*)(gp + (size_t)gr1 * FOUT_ + cl) =
            make_float2(E11 * accE[nt][2] + F11 * accF[nt][2],
                        E11 * accE[nt][3] + F11 * accF[nt][3]);
    }
    if (t < 64) g_den[jh][b * N_ + i0 + t] = s_den[t];
    __threadfence();
    __syncthreads();
    if (t == 0) s_old = atomicAdd(&g_cnt[tile], 1);
    __syncthreads();

    if (s_old == 1) {
        __threadfence();   // acquire: other CTA's partials now visible
        const float* go = g_part[jh ^ 1];
        const float* gdo = g_den[jh ^ 1];
        const float inv0 = 1.0f / (s_den[wm * 16 + g] + gdo[gr0]);
        const float inv1 = 1.0f / (s_den[wm * 16 + g + 8] + gdo[gr1]);
#pragma unroll
        for (int nt = 0; nt < 9; nt++) {
            if (wn == 1 && nt >= 7) break;
            const int cl = nbase + nt * 8 + 2 * tig;
            float2 o0 = *(const float2*)(go + (size_t)gr0 * FOUT_ + cl);
            float2 o1 = *(const float2*)(go + (size_t)gr1 * FOUT_ + cl);
            *(float2*)(out + (size_t)gr0 * FOUT_ + cl) = make_float2(
                (E10 * accE[nt][0] + F10 * accF[nt][0] + o0.x) * inv0,
                (E10 * accE[nt][1] + F10 * accF[nt][1] + o0.y) * inv0);
            *(float2*)(out + (size_t)gr1 * FOUT_ + cl) = make_float2(
                (E11 * accE[nt][2] + F11 * accF[nt][2] + o1.x) * inv1,
                (E11 * accE[nt][3] + F11 * accF[nt][3] + o1.y) * inv1);
        }
        if (t == 0) g_cnt[tile] = 0;   // reset for next graph replay
    }
}

// ---------------------------------------------------------------------------
extern "C" void kernel_launch(void* const* d_in, const int* in_sizes, int n_in,
                              void* d_out, int out_size) {
    const float* X   = (const float*)d_in[0];
    const float* W   = (const float*)d_in[1];
    const float* a1  = (const float*)d_in[2];
    const float* a2  = (const float*)d_in[3];
    const int*   adj = (const int*)d_in[4];
    // d_in[5] = adj_tree: unused by the reference forward
    const int* d1p = (const int*)d_in[6];
    const int* d2p = (const int*)d_in[7];
    float* out = (float*)d_out;

    cudaFuncSetAttribute(k_gemm_tc, cudaFuncAttributeMaxDynamicSharedMemorySize, GSM);
    k_gemm_tc<<<ROWS_TOT / 64, 256, GSM>>>(X, W, a1, a2);

    cudaFuncSetAttribute(k_attn_tc, cudaFuncAttributeMaxDynamicSharedMemorySize, ASM);
    k_attn_tc<<<B_ * 32 * 2, 256, ASM>>>(adj, d1p, d2p, out);
}

// round 11
// speedup vs baseline: 1.5354x; 1.2511x over previous
#include <cuda_runtime.h>
#include <cuda_bf16.h>
#include <cuda_fp16.h>
#include <cstdint>

#define B_    4
#define N_    2048
#define FIN_  512
#define FOUT_ 128
#define ROWS_TOT (B_ * N_)
#define PX    144
#define PW    272
#define PB2   144    // attn B tile pitch
#define TROWS 136    // 128 h rows + 1 ones row + 7 zero pad
#define TILE_B (TROWS * PB2)   // 19584

// ---------------- global scratch (no cudaMalloc allowed) --------------------
__device__ __align__(16) __half g_hH[B_ * TROWS * N_];  // [b][o][j] h fp16; row128=1
__device__ __align__(16) __half g_e2h[ROWS_TOT], g_f2h[ROWS_TOT];  // 0.25*E2/F2
__device__ __half g_e1h[ROWS_TOT], g_f1h[ROWS_TOT];                // 0.25*E1/F1
__device__ float g_t1[ROWS_TOT], g_t2[ROWS_TOT];
__device__ __align__(16) float g_part[2][ROWS_TOT * FOUT_];
__device__ float g_den[2][ROWS_TOT];
__device__ int   g_cnt[B_ * 32];

// ---------------- helpers ----------------------------------------------------
__device__ __forceinline__ void mma_bf16(float* c,
    uint32_t a0, uint32_t a1, uint32_t a2, uint32_t a3, uint32_t b0, uint32_t b1) {
    asm volatile(
        "mma.sync.aligned.m16n8k16.row.col.f32.bf16.bf16.f32 "
        "{%0,%1,%2,%3},{%4,%5,%6,%7},{%8,%9},{%0,%1,%2,%3};"
        : "+f"(c[0]), "+f"(c[1]), "+f"(c[2]), "+f"(c[3])
        : "r"(a0), "r"(a1), "r"(a2), "r"(a3), "r"(b0), "r"(b1));
}
__device__ __forceinline__ void mma_f16(float* c,
    uint32_t a0, uint32_t a1, uint32_t a2, uint32_t a3, uint32_t b0, uint32_t b1) {
    asm volatile(
        "mma.sync.aligned.m16n8k16.row.col.f32.f16.f16.f32 "
        "{%0,%1,%2,%3},{%4,%5,%6,%7},{%8,%9},{%0,%1,%2,%3};"
        : "+f"(c[0]), "+f"(c[1]), "+f"(c[2]), "+f"(c[3])
        : "r"(a0), "r"(a1), "r"(a2), "r"(a3), "r"(b0), "r"(b1));
}
#define LDM4(r0, r1, r2, r3, a)                                          \
    asm volatile("ldmatrix.sync.aligned.m8n8.x4.shared.b16 "             \
                 "{%0,%1,%2,%3},[%4];"                                   \
                 : "=r"(r0), "=r"(r1), "=r"(r2), "=r"(r3) : "r"(a))
#define LDM4T(r0, r1, r2, r3, a)                                         \
    asm volatile("ldmatrix.sync.aligned.m8n8.x4.trans.shared.b16 "       \
                 "{%0,%1,%2,%3},[%4];"                                   \
                 : "=r"(r0), "=r"(r1), "=r"(r2), "=r"(r3) : "r"(a))
__device__ __forceinline__ uint32_t bf2u(__nv_bfloat162 v) {
    return *reinterpret_cast<uint32_t*>(&v);
}
__device__ __forceinline__ void split2(float a, float b, uint32_t& hi, uint32_t& lo) {
    __nv_bfloat162 h = __floats2bfloat162_rn(a, b);
    __nv_bfloat162 l = __floats2bfloat162_rn(a - __bfloat162float(h.x),
                                             b - __bfloat162float(h.y));
    hi = bf2u(h); lo = bf2u(l);
}
__device__ __forceinline__ uint32_t h2u(__half2 v) {
    return *reinterpret_cast<uint32_t*>(&v);
}
#define CPASYNC16(dst, src) \
    asm volatile("cp.async.cg.shared.global [%0], [%1], 16;" :: "r"(dst), "l"(src))
#define CPCOMMIT() asm volatile("cp.async.commit_group;" ::: "memory")
#define CPWAIT(n)  asm volatile("cp.async.wait_group %0;" :: "n"(n) : "memory")
__device__ __forceinline__ uint32_t smem_u32(const void* p) {
    uint32_t a;
    asm("{ .reg .u64 t; cvta.to.shared.u64 t, %1; cvt.u32.u64 %0, t; }"
        : "=r"(a) : "l"(p));
    return a;
}

// ---------------------------------------------------------------------------
// K1: h = X @ W (bf16 hi/lo 3-MMA, proven). Epilogue: t1/t2, fp16 scale
// tables (0.25*E/F), and plain-fp16 h^T with ones row 128.
// ---------------------------------------------------------------------------
#define GXH 0
#define GXL 9216
#define GWH 18432
#define GWL 35840
#define GA1 53248
#define GA2 53760
#define GSM 54272

__global__ __launch_bounds__(256) void k_gemm_tc(const float* __restrict__ X,
                                                 const float* __restrict__ W,
                                                 const float* __restrict__ a1,
                                                 const float* __restrict__ a2) {
    extern __shared__ char sm[];
    const uint32_t smb = smem_u32(sm);
    const int t = threadIdx.x, w = t >> 5, lane = t & 31;
    const int wm = w & 3, wn = w >> 2;
    const int row0 = blockIdx.x * 64;

    if (t < 128) {
        ((float*)(sm + GA1))[t] = a1[t];
        ((float*)(sm + GA2))[t] = a2[t];
    }

    float acc[8][4];
#pragma unroll
    for (int nt = 0; nt < 8; nt++)
        acc[nt][0] = acc[nt][1] = acc[nt][2] = acc[nt][3] = 0.f;

    const uint32_t ax_off =
        (uint32_t)(wm * 16 + ((lane >> 3) & 1) * 8 + (lane & 7)) * PX +
        (lane >> 4) * 16;
    const uint32_t wl_row = (uint32_t)lane * PW;

    for (int c = 0; c < 8; c++) {
        const int kc = c * 64;
#pragma unroll
        for (int l = 0; l < 4; l++) {
            int f = t + l * 256;
            int m = f >> 4, kq = (f & 15) * 4;
            float4 v = *(const float4*)(X + (size_t)(row0 + m) * FIN_ + kc + kq);
            uint32_t h0, l0, h1, l1;
            split2(v.x, v.y, h0, l0);
            split2(v.z, v.w, h1, l1);
            *(uint2*)(sm + GXH + m * PX + kq * 2) = make_uint2(h0, h1);
            *(uint2*)(sm + GXL + m * PX + kq * 2) = make_uint2(l0, l1);
        }
#pragma unroll
        for (int l = 0; l < 8; l++) {
            int f = t + l * 256;
            int k = f >> 5, nq = (f & 31) * 4;
            float4 v = *(const float4*)(W + (size_t)(kc + k) * FOUT_ + nq);
            uint32_t h0, l0, h1, l1;
            split2(v.x, v.y, h0, l0);
            split2(v.z, v.w, h1, l1);
            *(uint2*)(sm + GWH + k * PW + nq * 2) = make_uint2(h0, h1);
            *(uint2*)(sm + GWL + k * PW + nq * 2) = make_uint2(l0, l1);
        }
        __syncthreads();

        uint32_t ah[4][4], al[4][4];
#pragma unroll
        for (int ks = 0; ks < 4; ks++) {
            LDM4(ah[ks][0], ah[ks][1], ah[ks][2], ah[ks][3],
                 smb + GXH + ax_off + ks * 32);
            LDM4(al[ks][0], al[ks][1], al[ks][2], al[ks][3],
                 smb + GXL + ax_off + ks * 32);
        }
#pragma unroll
        for (int nt = 0; nt < 8; nt++) {
            const int n0 = wn * 64 + nt * 8;
            const uint32_t wadr = smb + GWH + wl_row + n0 * 2;
            uint32_t bh[8], bl[8];
            LDM4T(bh[0], bh[1], bh[2], bh[3], wadr);
            LDM4T(bh[4], bh[5], bh[6], bh[7], wadr + 32 * PW);
            LDM4T(bl[0], bl[1], bl[2], bl[3], wadr + (GWL - GWH));
            LDM4T(bl[4], bl[5], bl[6], bl[7], wadr + (GWL - GWH) + 32 * PW);
#pragma unroll
            for (int ks = 0; ks < 4; ks++) {
                mma_bf16(acc[nt], ah[ks][0], ah[ks][1], ah[ks][2], ah[ks][3],
                         bh[2 * ks], bh[2 * ks + 1]);
                mma_bf16(acc[nt], ah[ks][0], ah[ks][1], ah[ks][2], ah[ks][3],
                         bl[2 * ks], bl[2 * ks + 1]);
                mma_bf16(acc[nt], al[ks][0], al[ks][1], al[ks][2], al[ks][3],
                         bh[2 * ks], bh[2 * ks + 1]);
            }
        }
        __syncthreads();
    }

    // ---- epilogue ----
    const int g = lane >> 2, tig = lane & 3;
    float* Ds = (float*)sm;
    {
        const int r = wm * 16 + g, cl = wn * 64 + 2 * tig;
#pragma unroll
        for (int nt = 0; nt < 8; nt++) {
            Ds[r * 132 + cl + nt * 8]           = acc[nt][0];
            Ds[r * 132 + cl + nt * 8 + 1]       = acc[nt][1];
            Ds[(r + 8) * 132 + cl + nt * 8]     = acc[nt][2];
            Ds[(r + 8) * 132 + cl + nt * 8 + 1] = acc[nt][3];
        }
    }
    __syncthreads();
    const float* A1 = (const float*)(sm + GA1);
    const float* A2 = (const float*)(sm + GA2);
#pragma unroll
    for (int rr = 0; rr < 8; rr++) {
        int r = w * 8 + rr;
        float s1 = 0.f, s2 = 0.f;
#pragma unroll
        for (int q = 0; q < 4; q++) {
            float v = Ds[r * 132 + lane + 32 * q];
            s1 = fmaf(v, A1[lane + 32 * q], s1);
            s2 = fmaf(v, A2[lane + 32 * q], s2);
        }
#pragma unroll
        for (int o = 16; o; o >>= 1) {
            s1 += __shfl_down_sync(0xffffffffu, s1, o);
            s2 += __shfl_down_sync(0xffffffffu, s2, o);
        }
        if (lane == 0) {
            int gr = row0 + r;
            g_t1[gr] = s1;  g_t2[gr] = s2;
            g_e1h[gr] = __float2half_rn(0.25f * expf(s1));
            g_f1h[gr] = __float2half_rn(0.25f * expf(0.2f * s1));
            g_e2h[gr] = __float2half_rn(0.25f * expf(s2));
            g_f2h[gr] = __float2half_rn(0.25f * expf(0.2f * s2));
        }
    }
    __syncthreads();
    {
        const int o = t & 127, half = t >> 7;
        const int bb = row0 >> 11, j0g = row0 & (N_ - 1);
        uint32_t uH[16];
#pragma unroll
        for (int ii = 0; ii < 16; ii++) {
            int j0l = half * 32 + 2 * ii;
            uH[ii] = h2u(__floats2half2_rn(Ds[j0l * 132 + o],
                                           Ds[(j0l + 1) * 132 + o]));
        }
        size_t base = ((size_t)(bb * TROWS) + o) * N_ + j0g + half * 32;
#pragma unroll
        for (int q = 0; q < 4; q++)
            *(uint4*)(g_hH + base + q * 8) =
                make_uint4(uH[4 * q], uH[4 * q + 1], uH[4 * q + 2], uH[4 * q + 3]);
        if (t < 64)
            g_hH[((size_t)(bb * TROWS) + 128) * N_ + j0g + t] = __float2half_rn(1.0f);
    }
}

// ---------------------------------------------------------------------------
// K2: attention, single fp16-P GEMM: [D | den] = P @ [h ; 1].
// j-split x2 + bit-mask prefill + cooperative A-staging (smem P tiles).
// ---------------------------------------------------------------------------
#define ASTG (2 * TILE_B)           // 39168
#define APB  144
#define ASZ  (64 * APB)             // 9216
#define MES  (ASTG + 2 * ASZ)       // 57600
#define MFS  (MES + 64 * 34 * 4)    // 66304
#define SE2  (MFS + 64 * 34 * 4)    // 75008
#define SF2  (SE2 + 2048)           // 77056
#define ASM2 (SF2 + 2048)           // 79104

__global__ __launch_bounds__(256, 2) void k_attn_tc(const int* __restrict__ adj,
                                                    const int* __restrict__ d1p,
                                                    const int* __restrict__ d2p,
                                                    float* __restrict__ out) {
    extern __shared__ char sm[];
    __shared__ float s_den[64];
    __shared__ int s_old;
    const uint32_t smb = smem_u32(sm);
    const int t = threadIdx.x, w = t >> 5, lane = t & 31;
    const int g = lane >> 2, tig = lane & 3;
    const int wm = w & 3, wn = w >> 2;
    const int tile = blockIdx.x >> 1, jh = blockIdx.x & 1;
    const int b = tile >> 5, i0 = (tile & 31) * 64;
    const int jbase = jh * 1024;
    const int d1 = *d1p, d2 = *d2p;

    const __half* gHb = g_hH + (size_t)b * TROWS * N_;

    auto load_chunk = [&](int j0, int buf) {
#pragma unroll
        for (int l = 0; l < 5; l++) {
            int f = t + l * 256;
            if (f < 1088) {
                int row = f >> 3, u = f & 7;
                const __half* src = gHb + (size_t)row * N_ + j0 + u * 8;
                uint32_t dst = smb + buf * TILE_B + row * PB2 + u * 16;
                CPASYNC16(dst, src);
            }
        }
    };

    load_chunk(jbase, 0);
    CPCOMMIT();

    // ---- PREFILL: adj slice -> bit masks (maskE = adj&pos, maskF = adj&~pos)
    {
        uint32_t* ME = (uint32_t*)(sm + MES);
        uint32_t* MF = (uint32_t*)(sm + MFS);
        const float* t2p = g_t2 + b * N_ + jbase;
#pragma unroll 1
        for (int rr = 0; rr < 8; rr++) {
            const int lr = w * 8 + rr;
            const float nt1 = -g_t1[b * N_ + i0 + lr];
            const int* arow = adj + (size_t)(b * N_ + i0 + lr) * N_ + jbase;
#pragma unroll 1
            for (int b8 = 0; b8 < 4; b8++) {
                int av[8]; float tv[8];
#pragma unroll
                for (int k = 0; k < 8; k++) {
                    av[k] = arow[(b8 * 8 + k) * 32 + lane];
                    tv[k] = t2p[(b8 * 8 + k) * 32 + lane];
                }
#pragma unroll
                for (int k = 0; k < 8; k++) {
                    bool m = (av[k] == d1) | (av[k] == d2);
                    bool p = tv[k] > nt1;
                    uint32_t bE = __ballot_sync(0xffffffffu, m & p);
                    uint32_t bF = __ballot_sync(0xffffffffu, m & (!p));
                    if (lane == 0) {
                        ME[lr * 34 + b8 * 8 + k] = bE;
                        MF[lr * 34 + b8 * 8 + k] = bF;
                    }
                }
            }
        }
    }

    // sc tables into smem
    __half* e2s = (__half*)(sm + SE2);
    __half* f2s = (__half*)(sm + SF2);
    if (t < 128) {
        ((uint4*)e2s)[t] = ((const uint4*)(g_e2h + b * N_ + jbase))[t];
        ((uint4*)f2s)[t] = ((const uint4*)(g_f2h + b * N_ + jbase))[t];
    }

    // expansion row constants
    const int rexp = t >> 2, ctexp = t & 3;
    const uint32_t e1lo = (uint32_t)__half_as_ushort(g_e1h[b * N_ + i0 + rexp]);
    const uint32_t f1lo = (uint32_t)__half_as_ushort(g_f1h[b * N_ + i0 + rexp]);
    const uint32_t e1hi = e1lo << 16, f1hi = f1lo << 16;

    __syncthreads();   // masks + sc visible

    const uint32_t* MEw = (const uint32_t*)(sm + MES);
    const uint32_t* MFw = (const uint32_t*)(sm + MFS);

    auto expand = [&](int cc, int ab) {
        uint32_t mE = (MEw[rexp * 34 + cc * 2 + (ctexp >> 1)] >> ((ctexp & 1) * 16)) & 0xffffu;
        uint32_t mF = (MFw[rexp * 34 + cc * 2 + (ctexp >> 1)] >> ((ctexp & 1) * 16)) & 0xffffu;
        const int jl = cc * 64 + ctexp * 16;
        uint4 ea = *(const uint4*)(e2s + jl);
        uint4 eb = *(const uint4*)(e2s + jl + 8);
        uint4 fa = *(const uint4*)(f2s + jl);
        uint4 fb = *(const uint4*)(f2s + jl + 8);
        uint32_t UE[8] = {ea.x, ea.y, ea.z, ea.w, eb.x, eb.y, eb.z, eb.w};
        uint32_t UF[8] = {fa.x, fa.y, fa.z, fa.w, fb.x, fb.y, fb.z, fb.w};
        uint32_t ow[8];
#pragma unroll
        for (int k = 0; k < 8; k++) {
            uint32_t pE = (mE >> (2 * k)) & 3u;
            uint32_t pU = pE | ((mF >> (2 * k)) & 3u);
            uint32_t m2 = ((pE & 1) ? (UE[k] & 0xffffu) : (UF[k] & 0xffffu))
                        | ((pE & 2) ? (UE[k] & 0xffff0000u) : (UF[k] & 0xffff0000u));
            uint32_t m1 = ((pE & 1) ? e1lo : f1lo) | ((pE & 2) ? e1hi : f1hi);
            uint32_t z  = ((pU & 1) ? 0xffffu : 0u) | ((pU & 2) ? 0xffff0000u : 0u);
            __half2 pr = __hmul2(*(__half2*)&m1, *(__half2*)&m2);
            ow[k] = (*(uint32_t*)&pr) & z;
        }
        char* dst = sm + ASTG + ab * ASZ + rexp * APB + ctexp * 32;
        *(uint4*)(dst)      = make_uint4(ow[0], ow[1], ow[2], ow[3]);
        *(uint4*)(dst + 16) = make_uint4(ow[4], ow[5], ow[6], ow[7]);
    };

    expand(0, 0);

    float acc[9][4];
#pragma unroll
    for (int nt = 0; nt < 9; nt++)
        acc[nt][0] = acc[nt][1] = acc[nt][2] = acc[nt][3] = 0.f;

    const int nbase = wn ? 72 : 0;
    const uint32_t bloff = (uint32_t)(lane & 7) * PB2 + (lane >> 3) * 16;
    const uint32_t aloff = (uint32_t)((lane & 15) + wm * 16) * APB + (lane >> 4) * 16;

    for (int c = 0; c < 16; c++) {
        const int buf = c & 1;
        CPWAIT(0);
        __syncthreads();   // B_c + A-stage_c visible; prev bufs drained
        if (c + 1 < 16) {
            load_chunk(jbase + (c + 1) * 64, buf ^ 1);
            CPCOMMIT();
            expand(c + 1, buf ^ 1);
        }

        uint32_t aH[4][4];
#pragma unroll
        for (int ks = 0; ks < 4; ks++)
            LDM4(aH[ks][0], aH[ks][1], aH[ks][2], aH[ks][3],
                 smb + ASTG + buf * ASZ + aloff + ks * 32);

        const uint32_t base = smb + buf * TILE_B + bloff;
#pragma unroll
        for (int ga = 0; ga < 2; ga++) {
            uint32_t bb[2][4];
            LDM4(bb[0][0], bb[0][1], bb[0][2], bb[0][3],
                 base + (uint32_t)nbase * PB2 + ga * 64);
#pragma unroll
            for (int nt = 0; nt < 9; nt++) {
                const int cur = nt & 1, nxt = cur ^ 1;
                if (nt < 8)
                    LDM4(bb[nxt][0], bb[nxt][1], bb[nxt][2], bb[nxt][3],
                         base + (uint32_t)(nbase + (nt + 1) * 8) * PB2 + ga * 64);
                if (nt < 8 || !wn) {
                    mma_f16(acc[nt], aH[2 * ga][0], aH[2 * ga][1],
                            aH[2 * ga][2], aH[2 * ga][3], bb[cur][0], bb[cur][1]);
                    mma_f16(acc[nt], aH[2 * ga + 1][0], aH[2 * ga + 1][1],
                            aH[2 * ga + 1][2], aH[2 * ga + 1][3], bb[cur][2], bb[cur][3]);
                }
            }
        }
    }

    const int r0 = i0 + wm * 16 + g, r1 = r0 + 8;
    const int gr0 = b * N_ + r0, gr1 = b * N_ + r1;

    // ---- partial denominators: col 128 = wn1 tile nt7, elems 0/2 ----
    if (wn == 1 && tig == 0) {
        s_den[wm * 16 + g]     = acc[7][0];
        s_den[wm * 16 + g + 8] = acc[7][2];
    }
    __syncthreads();

    float* gp = g_part[jh];
#pragma unroll
    for (int nt = 0; nt < 9; nt++) {
        if (wn == 1 && nt >= 7) break;
        const int cl = nbase + nt * 8 + 2 * tig;
        *(float2*)(gp + (size_t)gr0 * FOUT_ + cl) = make_float2(acc[nt][0], acc[nt][1]);
        *(float2*)(gp + (size_t)gr1 * FOUT_ + cl) = make_float2(acc[nt][2], acc[nt][3]);
    }
    if (t < 64) g_den[jh][b * N_ + i0 + t] = s_den[t];
    __threadfence();
    __syncthreads();
    if (t == 0) s_old = atomicAdd(&g_cnt[tile], 1);
    __syncthreads();

    if (s_old == 1) {
        __threadfence();
        const float* go = g_part[jh ^ 1];
        const float* gdo = g_den[jh ^ 1];
        const float inv0 = 1.0f / (s_den[wm * 16 + g] + gdo[gr0]);
        const float inv1 = 1.0f / (s_den[wm * 16 + g + 8] + gdo[gr1]);
#pragma unroll
        for (int nt = 0; nt < 9; nt++) {
            if (wn == 1 && nt >= 7) break;
            const int cl = nbase + nt * 8 + 2 * tig;
            float2 o0 = *(const float2*)(go + (size_t)gr0 * FOUT_ + cl);
            float2 o1 = *(const float2*)(go + (size_t)gr1 * FOUT_ + cl);
            *(float2*)(out + (size_t)gr0 * FOUT_ + cl) =
                make_float2((acc[nt][0] + o0.x) * inv0, (acc[nt][1] + o0.y) * inv0);
            *(float2*)(out + (size_t)gr1 * FOUT_ + cl) =
                make_float2((acc[nt][2] + o1.x) * inv1, (acc[nt][3] + o1.y) * inv1);
        }
        if (t == 0) g_cnt[tile] = 0;
    }
}

// ---------------------------------------------------------------------------
extern "C" void kernel_launch(void* const* d_in, const int* in_sizes, int n_in,
                              void* d_out, int out_size) {
    const float* X   = (const float*)d_in[0];
    const float* W   = (const float*)d_in[1];
    const float* a1  = (const float*)d_in[2];
    const float* a2  = (const float*)d_in[3];
    const int*   adj = (const int*)d_in[4];
    // d_in[5] = adj_tree: unused by the reference forward
    const int* d1p = (const int*)d_in[6];
    const int* d2p = (const int*)d_in[7];
    float* out = (float*)d_out;

    cudaFuncSetAttribute(k_gemm_tc, cudaFuncAttributeMaxDynamicSharedMemorySize, GSM);
    k_gemm_tc<<<ROWS_TOT / 64, 256, GSM>>>(X, W, a1, a2);

    cudaFuncSetAttribute(k_attn_tc, cudaFuncAttributeMaxDynamicSharedMemorySize, ASM2);
    k_attn_tc<<<B_ * 32 * 2, 256, ASM2>>>(adj, d1p, d2p, out);
}

// round 12
// speedup vs baseline: 1.6652x; 1.0846x over previous
#include <cuda_runtime.h>
#include <cuda_bf16.h>
#include <cuda_fp16.h>
#include <cstdint>

#define B_    4
#define N_    2048
#define FIN_  512
#define FOUT_ 128
#define ROWS_TOT (B_ * N_)
#define PX    144
#define PW    272
#define PB2   144    // attn B tile pitch
#define TROWS 136    // 128 h rows + 1 ones row + 7 zero pad
#define TILE_B (TROWS * PB2)   // 19584

// ---------------- global scratch (no cudaMalloc allowed) --------------------
__device__ __align__(16) __half g_hH[B_ * TROWS * N_];  // [b][o][j] h fp16; row128=1
__device__ __align__(16) __half g_e2h[ROWS_TOT], g_f2h[ROWS_TOT];  // 0.25*E2/F2
__device__ __half g_e1h[ROWS_TOT], g_f1h[ROWS_TOT];                // 0.25*E1/F1
__device__ float g_t1[ROWS_TOT], g_t2[ROWS_TOT];
__device__ __align__(16) float g_part[2][ROWS_TOT * FOUT_];
__device__ float g_den[2][ROWS_TOT];
__device__ int   g_cnt[B_ * 32];

// ---------------- helpers ----------------------------------------------------
__device__ __forceinline__ void mma_bf16(float* c,
    uint32_t a0, uint32_t a1, uint32_t a2, uint32_t a3, uint32_t b0, uint32_t b1) {
    asm volatile(
        "mma.sync.aligned.m16n8k16.row.col.f32.bf16.bf16.f32 "
        "{%0,%1,%2,%3},{%4,%5,%6,%7},{%8,%9},{%0,%1,%2,%3};"
        : "+f"(c[0]), "+f"(c[1]), "+f"(c[2]), "+f"(c[3])
        : "r"(a0), "r"(a1), "r"(a2), "r"(a3), "r"(b0), "r"(b1));
}
__device__ __forceinline__ void mma_f16(float* c,
    uint32_t a0, uint32_t a1, uint32_t a2, uint32_t a3, uint32_t b0, uint32_t b1) {
    asm volatile(
        "mma.sync.aligned.m16n8k16.row.col.f32.f16.f16.f32 "
        "{%0,%1,%2,%3},{%4,%5,%6,%7},{%8,%9},{%0,%1,%2,%3};"
        : "+f"(c[0]), "+f"(c[1]), "+f"(c[2]), "+f"(c[3])
        : "r"(a0), "r"(a1), "r"(a2), "r"(a3), "r"(b0), "r"(b1));
}
#define LDM4(r0, r1, r2, r3, a)                                          \
    asm volatile("ldmatrix.sync.aligned.m8n8.x4.shared.b16 "             \
                 "{%0,%1,%2,%3},[%4];"                                   \
                 : "=r"(r0), "=r"(r1), "=r"(r2), "=r"(r3) : "r"(a))
#define LDM4T(r0, r1, r2, r3, a)                                         \
    asm volatile("ldmatrix.sync.aligned.m8n8.x4.trans.shared.b16 "       \
                 "{%0,%1,%2,%3},[%4];"                                   \
                 : "=r"(r0), "=r"(r1), "=r"(r2), "=r"(r3) : "r"(a))
__device__ __forceinline__ uint32_t bf2u(__nv_bfloat162 v) {
    return *reinterpret_cast<uint32_t*>(&v);
}
__device__ __forceinline__ void split2(float a, float b, uint32_t& hi, uint32_t& lo) {
    __nv_bfloat162 h = __floats2bfloat162_rn(a, b);
    __nv_bfloat162 l = __floats2bfloat162_rn(a - __bfloat162float(h.x),
                                             b - __bfloat162float(h.y));
    hi = bf2u(h); lo = bf2u(l);
}
__device__ __forceinline__ uint32_t h2u(__half2 v) {
    return *reinterpret_cast<uint32_t*>(&v);
}
#define CPASYNC16(dst, src) \
    asm volatile("cp.async.cg.shared.global [%0], [%1], 16;" :: "r"(dst), "l"(src))
#define CPCOMMIT() asm volatile("cp.async.commit_group;" ::: "memory")
#define CPWAIT(n)  asm volatile("cp.async.wait_group %0;" :: "n"(n) : "memory")
__device__ __forceinline__ uint32_t smem_u32(const void* p) {
    uint32_t a;
    asm("{ .reg .u64 t; cvta.to.shared.u64 t, %1; cvt.u32.u64 %0, t; }"
        : "=r"(a) : "l"(p));
    return a;
}

// ---------------------------------------------------------------------------
// K1: h = X @ W (bf16 hi/lo 3-MMA, proven). Epilogue: t1/t2, fp16 scale
// tables (0.25*E/F), and plain-fp16 h^T with ones row 128. (R11 verbatim)
// ---------------------------------------------------------------------------
#define GXH 0
#define GXL 9216
#define GWH 18432
#define GWL 35840
#define GA1 53248
#define GA2 53760
#define GSM 54272

__global__ __launch_bounds__(256) void k_gemm_tc(const float* __restrict__ X,
                                                 const float* __restrict__ W,
                                                 const float* __restrict__ a1,
                                                 const float* __restrict__ a2) {
    extern __shared__ char sm[];
    const uint32_t smb = smem_u32(sm);
    const int t = threadIdx.x, w = t >> 5, lane = t & 31;
    const int wm = w & 3, wn = w >> 2;
    const int row0 = blockIdx.x * 64;

    if (t < 128) {
        ((float*)(sm + GA1))[t] = a1[t];
        ((float*)(sm + GA2))[t] = a2[t];
    }

    float acc[8][4];
#pragma unroll
    for (int nt = 0; nt < 8; nt++)
        acc[nt][0] = acc[nt][1] = acc[nt][2] = acc[nt][3] = 0.f;

    const uint32_t ax_off =
        (uint32_t)(wm * 16 + ((lane >> 3) & 1) * 8 + (lane & 7)) * PX +
        (lane >> 4) * 16;
    const uint32_t wl_row = (uint32_t)lane * PW;

    for (int c = 0; c < 8; c++) {
        const int kc = c * 64;
#pragma unroll
        for (int l = 0; l < 4; l++) {
            int f = t + l * 256;
            int m = f >> 4, kq = (f & 15) * 4;
            float4 v = *(const float4*)(X + (size_t)(row0 + m) * FIN_ + kc + kq);
            uint32_t h0, l0, h1, l1;
            split2(v.x, v.y, h0, l0);
            split2(v.z, v.w, h1, l1);
            *(uint2*)(sm + GXH + m * PX + kq * 2) = make_uint2(h0, h1);
            *(uint2*)(sm + GXL + m * PX + kq * 2) = make_uint2(l0, l1);
        }
#pragma unroll
        for (int l = 0; l < 8; l++) {
            int f = t + l * 256;
            int k = f >> 5, nq = (f & 31) * 4;
            float4 v = *(const float4*)(W + (size_t)(kc + k) * FOUT_ + nq);
            uint32_t h0, l0, h1, l1;
            split2(v.x, v.y, h0, l0);
            split2(v.z, v.w, h1, l1);
            *(uint2*)(sm + GWH + k * PW + nq * 2) = make_uint2(h0, h1);
            *(uint2*)(sm + GWL + k * PW + nq * 2) = make_uint2(l0, l1);
        }
        __syncthreads();

        uint32_t ah[4][4], al[4][4];
#pragma unroll
        for (int ks = 0; ks < 4; ks++) {
            LDM4(ah[ks][0], ah[ks][1], ah[ks][2], ah[ks][3],
                 smb + GXH + ax_off + ks * 32);
            LDM4(al[ks][0], al[ks][1], al[ks][2], al[ks][3],
                 smb + GXL + ax_off + ks * 32);
        }
#pragma unroll
        for (int nt = 0; nt < 8; nt++) {
            const int n0 = wn * 64 + nt * 8;
            const uint32_t wadr = smb + GWH + wl_row + n0 * 2;
            uint32_t bh[8], bl[8];
            LDM4T(bh[0], bh[1], bh[2], bh[3], wadr);
            LDM4T(bh[4], bh[5], bh[6], bh[7], wadr + 32 * PW);
            LDM4T(bl[0], bl[1], bl[2], bl[3], wadr + (GWL - GWH));
            LDM4T(bl[4], bl[5], bl[6], bl[7], wadr + (GWL - GWH) + 32 * PW);
#pragma unroll
            for (int ks = 0; ks < 4; ks++) {
                mma_bf16(acc[nt], ah[ks][0], ah[ks][1], ah[ks][2], ah[ks][3],
                         bh[2 * ks], bh[2 * ks + 1]);
                mma_bf16(acc[nt], ah[ks][0], ah[ks][1], ah[ks][2], ah[ks][3],
                         bl[2 * ks], bl[2 * ks + 1]);
                mma_bf16(acc[nt], al[ks][0], al[ks][1], al[ks][2], al[ks][3],
                         bh[2 * ks], bh[2 * ks + 1]);
            }
        }
        __syncthreads();
    }

    // ---- epilogue ----
    const int g = lane >> 2, tig = lane & 3;
    float* Ds = (float*)sm;
    {
        const int r = wm * 16 + g, cl = wn * 64 + 2 * tig;
#pragma unroll
        for (int nt = 0; nt < 8; nt++) {
            Ds[r * 132 + cl + nt * 8]           = acc[nt][0];
            Ds[r * 132 + cl + nt * 8 + 1]       = acc[nt][1];
            Ds[(r + 8) * 132 + cl + nt * 8]     = acc[nt][2];
            Ds[(r + 8) * 132 + cl + nt * 8 + 1] = acc[nt][3];
        }
    }
    __syncthreads();
    const float* A1 = (const float*)(sm + GA1);
    const float* A2 = (const float*)(sm + GA2);
#pragma unroll
    for (int rr = 0; rr < 8; rr++) {
        int r = w * 8 + rr;
        float s1 = 0.f, s2 = 0.f;
#pragma unroll
        for (int q = 0; q < 4; q++) {
            float v = Ds[r * 132 + lane + 32 * q];
            s1 = fmaf(v, A1[lane + 32 * q], s1);
            s2 = fmaf(v, A2[lane + 32 * q], s2);
        }
#pragma unroll
        for (int o = 16; o; o >>= 1) {
            s1 += __shfl_down_sync(0xffffffffu, s1, o);
            s2 += __shfl_down_sync(0xffffffffu, s2, o);
        }
        if (lane == 0) {
            int gr = row0 + r;
            g_t1[gr] = s1;  g_t2[gr] = s2;
            g_e1h[gr] = __float2half_rn(0.25f * expf(s1));
            g_f1h[gr] = __float2half_rn(0.25f * expf(0.2f * s1));
            g_e2h[gr] = __float2half_rn(0.25f * expf(s2));
            g_f2h[gr] = __float2half_rn(0.25f * expf(0.2f * s2));
        }
    }
    __syncthreads();
    {
        const int o = t & 127, half = t >> 7;
        const int bb = row0 >> 11, j0g = row0 & (N_ - 1);
        uint32_t uH[16];
#pragma unroll
        for (int ii = 0; ii < 16; ii++) {
            int j0l = half * 32 + 2 * ii;
            uH[ii] = h2u(__floats2half2_rn(Ds[j0l * 132 + o],
                                           Ds[(j0l + 1) * 132 + o]));
        }
        size_t base = ((size_t)(bb * TROWS) + o) * N_ + j0g + half * 32;
#pragma unroll
        for (int q = 0; q < 4; q++)
            *(uint4*)(g_hH + base + q * 8) =
                make_uint4(uH[4 * q], uH[4 * q + 1], uH[4 * q + 2], uH[4 * q + 3]);
        if (t < 64)
            g_hH[((size_t)(bb * TROWS) + 128) * N_ + j0g + t] = __float2half_rn(1.0f);
    }
}

// ---------------------------------------------------------------------------
// K2: attention, single fp16-P GEMM [D|den] = P @ [h;1].
// NO prefill: adj fused into the cooperative expand (vector LDG prefetched
// one chunk ahead, latency hidden under the MMA phase).
// ---------------------------------------------------------------------------
#define ASTG (2 * TILE_B)           // 39168
#define APB  144
#define ASZ  (64 * APB)             // 9216
#define ST2  (ASTG + 2 * ASZ)       // 57600: t2 fp32 [1024]
#define SE2  (ST2 + 4096)           // 61696: 0.25*E2 fp16 [1024]
#define SF2  (SE2 + 2048)           // 63744: 0.25*F2 fp16 [1024]
#define ASM2 (SF2 + 2048)           // 65792 total dynamic

__global__ __launch_bounds__(256, 2) void k_attn_tc(const int* __restrict__ adj,
                                                    const int* __restrict__ d1p,
                                                    const int* __restrict__ d2p,
                                                    float* __restrict__ out) {
    extern __shared__ char sm[];
    __shared__ float s_den[64];
    __shared__ int s_old;
    const uint32_t smb = smem_u32(sm);
    const int t = threadIdx.x, w = t >> 5, lane = t & 31;
    const int g = lane >> 2, tig = lane & 3;
    const int wm = w & 3, wn = w >> 2;
    const int tile = blockIdx.x >> 1, jh = blockIdx.x & 1;
    const int b = tile >> 5, i0 = (tile & 31) * 64;
    const int jbase = jh * 1024;
    const int d1 = *d1p, d2 = *d2p;

    const __half* gHb = g_hH + (size_t)b * TROWS * N_;

    auto load_chunk = [&](int j0, int buf) {
#pragma unroll
        for (int l = 0; l < 5; l++) {
            int f = t + l * 256;
            if (f < 1088) {
                int row = f >> 3, u = f & 7;
                const __half* src = gHb + (size_t)row * N_ + j0 + u * 8;
                uint32_t dst = smb + buf * TILE_B + row * PB2 + u * 16;
                CPASYNC16(dst, src);
            }
        }
    };

    load_chunk(jbase, 0);
    CPCOMMIT();

    // ---- tables into smem: t2 (fp32), 0.25*E2/F2 (fp16) for this j-half ----
    ((float4*)(sm + ST2))[t] = ((const float4*)(g_t2 + b * N_ + jbase))[t];
    if (t < 128)
        ((uint4*)(sm + SE2))[t] = ((const uint4*)(g_e2h + b * N_ + jbase))[t];
    else
        ((uint4*)(sm + SF2))[t - 128] =
            ((const uint4*)(g_f2h + b * N_ + jbase))[t - 128];

    // ---- expansion row constants ----
    const int rexp = t >> 2, ctexp = t & 3;
    const int gadj = b * N_ + i0 + rexp;
    const float nt1r = -g_t1[gadj];
    const uint32_t e1lo = (uint32_t)__half_as_ushort(g_e1h[gadj]);
    const uint32_t f1lo = (uint32_t)__half_as_ushort(g_f1h[gadj]);
    const uint32_t e1hi = e1lo << 16, f1hi = f1lo << 16;
    const int* adjrow = adj + (size_t)gadj * N_ + jbase + ctexp * 16;

    auto expand = [&](int4 q0, int4 q1, int4 q2, int4 q3, int cc, int ab) {
        const int jl = cc * 64 + ctexp * 16;
        const float* tp = (const float*)(sm + ST2) + jl;
        float4 t0 = *(const float4*)(tp);
        float4 t1v = *(const float4*)(tp + 4);
        float4 t2v = *(const float4*)(tp + 8);
        float4 t3 = *(const float4*)(tp + 12);
        float tf[16] = {t0.x, t0.y, t0.z, t0.w, t1v.x, t1v.y, t1v.z, t1v.w,
                        t2v.x, t2v.y, t2v.z, t2v.w, t3.x, t3.y, t3.z, t3.w};
        uint4 ea = *(const uint4*)((const __half*)(sm + SE2) + jl);
        uint4 eb = *(const uint4*)((const __half*)(sm + SE2) + jl + 8);
        uint4 fa = *(const uint4*)((const __half*)(sm + SF2) + jl);
        uint4 fb = *(const uint4*)((const __half*)(sm + SF2) + jl + 8);
        uint32_t UE[8] = {ea.x, ea.y, ea.z, ea.w, eb.x, eb.y, eb.z, eb.w};
        uint32_t UF[8] = {fa.x, fa.y, fa.z, fa.w, fb.x, fb.y, fb.z, fb.w};
        int av[16] = {q0.x, q0.y, q0.z, q0.w, q1.x, q1.y, q1.z, q1.w,
                      q2.x, q2.y, q2.z, q2.w, q3.x, q3.y, q3.z, q3.w};
        uint32_t ow[8];
#pragma unroll
        for (int k = 0; k < 8; k++) {
            int a0 = av[2 * k], a1 = av[2 * k + 1];
            bool m0 = (a0 == d1) | (a0 == d2);
            bool m1 = (a1 == d1) | (a1 == d2);
            bool p0 = tf[2 * k] > nt1r;
            bool p1 = tf[2 * k + 1] > nt1r;
            uint32_t s2 = (p0 ? (UE[k] & 0xffffu) : (UF[k] & 0xffffu))
                        | (p1 ? (UE[k] & 0xffff0000u) : (UF[k] & 0xffff0000u));
            uint32_t s1 = (p0 ? e1lo : f1lo) | (p1 ? e1hi : f1hi);
            __half2 pr = __hmul2(*(__half2*)&s1, *(__half2*)&s2);
            uint32_t z = (m0 ? 0xffffu : 0u) | (m1 ? 0xffff0000u : 0u);
            ow[k] = (*(uint32_t*)&pr) & z;
        }
        char* dst = sm + ASTG + ab * ASZ + rexp * APB + ctexp * 32;
        *(uint4*)(dst)      = make_uint4(ow[0], ow[1], ow[2], ow[3]);
        *(uint4*)(dst + 16) = make_uint4(ow[4], ow[5], ow[6], ow[7]);
    };

    // preload adj for chunk 0 (LDG latency overlaps table stores + barrier)
    int4 q0 = *(const int4*)(adjrow);
    int4 q1 = *(const int4*)(adjrow + 4);
    int4 q2 = *(const int4*)(adjrow + 8);
    int4 q3 = *(const int4*)(adjrow + 12);

    __syncthreads();      // tables visible
    expand(q0, q1, q2, q3, 0, 0);

    float acc[9][4];
#pragma unroll
    for (int nt = 0; nt < 9; nt++)
        acc[nt][0] = acc[nt][1] = acc[nt][2] = acc[nt][3] = 0.f;

    const int nbase = wn ? 72 : 0;
    const uint32_t bloff = (uint32_t)(lane & 7) * PB2 + (lane >> 3) * 16;
    const uint32_t aloff = (uint32_t)((lane & 15) + wm * 16) * APB + (lane >> 4) * 16;

    for (int c = 0; c < 16; c++) {
        const int buf = c & 1;
        CPWAIT(0);
        __syncthreads();   // B_c + A-stage_c visible; prev bufs drained
        if (c + 1 < 16) {
            load_chunk(jbase + (c + 1) * 64, buf ^ 1);
            CPCOMMIT();
            const int* ap = adjrow + (c + 1) * 64;   // prefetch adj(c+1)
            q0 = *(const int4*)(ap);
            q1 = *(const int4*)(ap + 4);
            q2 = *(const int4*)(ap + 8);
            q3 = *(const int4*)(ap + 12);
        }

        uint32_t aH[4][4];
#pragma unroll
        for (int ks = 0; ks < 4; ks++)
            LDM4(aH[ks][0], aH[ks][1], aH[ks][2], aH[ks][3],
                 smb + ASTG + buf * ASZ + aloff + ks * 32);

        const uint32_t base = smb + buf * TILE_B + bloff;
#pragma unroll
        for (int ga = 0; ga < 2; ga++) {
            uint32_t bb[2][4];
            LDM4(bb[0][0], bb[0][1], bb[0][2], bb[0][3],
                 base + (uint32_t)nbase * PB2 + ga * 64);
#pragma unroll
            for (int nt = 0; nt < 9; nt++) {
                const int cur = nt & 1, nxt = cur ^ 1;
                if (nt < 8)
                    LDM4(bb[nxt][0], bb[nxt][1], bb[nxt][2], bb[nxt][3],
                         base + (uint32_t)(nbase + (nt + 1) * 8) * PB2 + ga * 64);
                if (nt < 8 || !wn) {
                    mma_f16(acc[nt], aH[2 * ga][0], aH[2 * ga][1],
                            aH[2 * ga][2], aH[2 * ga][3], bb[cur][0], bb[cur][1]);
                    mma_f16(acc[nt], aH[2 * ga + 1][0], aH[2 * ga + 1][1],
                            aH[2 * ga + 1][2], aH[2 * ga + 1][3], bb[cur][2], bb[cur][3]);
                }
            }
        }

        if (c + 1 < 16)
            expand(q0, q1, q2, q3, c + 1, buf ^ 1);   // adj landed during MMAs
    }

    const int r0 = i0 + wm * 16 + g, r1 = r0 + 8;
    const int gr0 = b * N_ + r0, gr1 = b * N_ + r1;

    // ---- partial denominators: col 128 = wn1 tile nt7, elems 0/2 ----
    if (wn == 1 && tig == 0) {
        s_den[wm * 16 + g]     = acc[7][0];
        s_den[wm * 16 + g + 8] = acc[7][2];
    }
    __syncthreads();

    float* gp = g_part[jh];
#pragma unroll
    for (int nt = 0; nt < 9; nt++) {
        if (wn == 1 && nt >= 7) break;
        const int cl = nbase + nt * 8 + 2 * tig;
        *(float2*)(gp + (size_t)gr0 * FOUT_ + cl) = make_float2(acc[nt][0], acc[nt][1]);
        *(float2*)(gp + (size_t)gr1 * FOUT_ + cl) = make_float2(acc[nt][2], acc[nt][3]);
    }
    if (t < 64) g_den[jh][b * N_ + i0 + t] = s_den[t];
    __threadfence();
    __syncthreads();
    if (t == 0) s_old = atomicAdd(&g_cnt[tile], 1);
    __syncthreads();

    if (s_old == 1) {
        __threadfence();
        const float* go = g_part[jh ^ 1];
        const float* gdo = g_den[jh ^ 1];
        const float inv0 = 1.0f / (s_den[wm * 16 + g] + gdo[gr0]);
        const float inv1 = 1.0f / (s_den[wm * 16 + g + 8] + gdo[gr1]);
#pragma unroll
        for (int nt = 0; nt < 9; nt++) {
            if (wn == 1 && nt >= 7) break;
            const int cl = nbase + nt * 8 + 2 * tig;
            float2 o0 = *(const float2*)(go + (size_t)gr0 * FOUT_ + cl);
            float2 o1 = *(const float2*)(go + (size_t)gr1 * FOUT_ + cl);
            *(float2*)(out + (size_t)gr0 * FOUT_ + cl) =
                make_float2((acc[nt][0] + o0.x) * inv0, (acc[nt][1] + o0.y) * inv0);
            *(float2*)(out + (size_t)gr1 * FOUT_ + cl) =
                make_float2((acc[nt][2] + o1.x) * inv1, (acc[nt][3] + o1.y) * inv1);
        }
        if (t == 0) g_cnt[tile] = 0;
    }
}

// ---------------------------------------------------------------------------
extern "C" void kernel_launch(void* const* d_in, const int* in_sizes, int n_in,
                              void* d_out, int out_size) {
    const float* X   = (const float*)d_in[0];
    const float* W   = (const float*)d_in[1];
    const float* a1  = (const float*)d_in[2];
    const float* a2  = (const float*)d_in[3];
    const int*   adj = (const int*)d_in[4];
    // d_in[5] = adj_tree: unused by the reference forward
    const int* d1p = (const int*)d_in[6];
    const int* d2p = (const int*)d_in[7];
    float* out = (float*)d_out;

    cudaFuncSetAttribute(k_gemm_tc, cudaFuncAttributeMaxDynamicSharedMemorySize, GSM);
    k_gemm_tc<<<ROWS_TOT / 64, 256, GSM>>>(X, W, a1, a2);

    cudaFuncSetAttribute(k_attn_tc, cudaFuncAttributeMaxDynamicSharedMemorySize, ASM2);
    k_attn_tc<<<B_ * 32 * 2, 256, ASM2>>>(adj, d1p, d2p, out);
}

// round 13
// speedup vs baseline: 1.7574x; 1.0554x over previous
#include <cuda_runtime.h>
#include <cuda_bf16.h>
#include <cuda_fp16.h>
#include <cstdint>

#define B_    4
#define N_    2048
#define FIN_  512
#define FOUT_ 128
#define ROWS_TOT (B_ * N_)
#define PX    144
#define PW    272
#define PB2   144    // attn B tile pitch
#define TROWS 136    // 128 h rows + 1 ones row + 7 zero pad
#define TILE_B (TROWS * PB2)   // 19584

// ---------------- global scratch (no cudaMalloc allowed) --------------------
__device__ __align__(16) __half g_hH[B_ * TROWS * N_];  // [b][o][j] h fp16; row128=1
__device__ __align__(16) __half g_e2h[ROWS_TOT], g_f2h[ROWS_TOT];  // 0.25*E2/F2
__device__ __half g_e1h[ROWS_TOT], g_f1h[ROWS_TOT];                // 0.25*E1/F1
__device__ float g_t1[ROWS_TOT], g_t2[ROWS_TOT];
__device__ __align__(16) float g_part[2][ROWS_TOT * FOUT_];
__device__ float g_den[2][ROWS_TOT];
__device__ int   g_cnt[B_ * 32];

// ---------------- helpers ----------------------------------------------------
__device__ __forceinline__ void mma_bf16(float* c,
    uint32_t a0, uint32_t a1, uint32_t a2, uint32_t a3, uint32_t b0, uint32_t b1) {
    asm volatile(
        "mma.sync.aligned.m16n8k16.row.col.f32.bf16.bf16.f32 "
        "{%0,%1,%2,%3},{%4,%5,%6,%7},{%8,%9},{%0,%1,%2,%3};"
        : "+f"(c[0]), "+f"(c[1]), "+f"(c[2]), "+f"(c[3])
        : "r"(a0), "r"(a1), "r"(a2), "r"(a3), "r"(b0), "r"(b1));
}
__device__ __forceinline__ void mma_f16(float* c,
    uint32_t a0, uint32_t a1, uint32_t a2, uint32_t a3, uint32_t b0, uint32_t b1) {
    asm volatile(
        "mma.sync.aligned.m16n8k16.row.col.f32.f16.f16.f32 "
        "{%0,%1,%2,%3},{%4,%5,%6,%7},{%8,%9},{%0,%1,%2,%3};"
        : "+f"(c[0]), "+f"(c[1]), "+f"(c[2]), "+f"(c[3])
        : "r"(a0), "r"(a1), "r"(a2), "r"(a3), "r"(b0), "r"(b1));
}
#define LDM4(r0, r1, r2, r3, a)                                          \
    asm volatile("ldmatrix.sync.aligned.m8n8.x4.shared.b16 "             \
                 "{%0,%1,%2,%3},[%4];"                                   \
                 : "=r"(r0), "=r"(r1), "=r"(r2), "=r"(r3) : "r"(a))
#define LDM4T(r0, r1, r2, r3, a)                                         \
    asm volatile("ldmatrix.sync.aligned.m8n8.x4.trans.shared.b16 "       \
                 "{%0,%1,%2,%3},[%4];"                                   \
                 : "=r"(r0), "=r"(r1), "=r"(r2), "=r"(r3) : "r"(a))
__device__ __forceinline__ uint32_t bf2u(__nv_bfloat162 v) {
    return *reinterpret_cast<uint32_t*>(&v);
}
__device__ __forceinline__ void split2(float a, float b, uint32_t& hi, uint32_t& lo) {
    __nv_bfloat162 h = __floats2bfloat162_rn(a, b);
    __nv_bfloat162 l = __floats2bfloat162_rn(a - __bfloat162float(h.x),
                                             b - __bfloat162float(h.y));
    hi = bf2u(h); lo = bf2u(l);
}
__device__ __forceinline__ uint32_t h2u(__half2 v) {
    return *reinterpret_cast<uint32_t*>(&v);
}
#define CPASYNC16(dst, src) \
    asm volatile("cp.async.cg.shared.global [%0], [%1], 16;" :: "r"(dst), "l"(src))
#define CPCOMMIT() asm volatile("cp.async.commit_group;" ::: "memory")
#define CPWAIT(n)  asm volatile("cp.async.wait_group %0;" :: "n"(n) : "memory")
__device__ __forceinline__ uint32_t smem_u32(const void* p) {
    uint32_t a;
    asm("{ .reg .u64 t; cvta.to.shared.u64 t, %1; cvt.u32.u64 %0, t; }"
        : "=r"(a) : "l"(p));
    return a;
}

// ---------------------------------------------------------------------------
// K1: h = X @ W (bf16 hi/lo 3-MMA, proven, R11/R12 verbatim).
// ---------------------------------------------------------------------------
#define GXH 0
#define GXL 9216
#define GWH 18432
#define GWL 35840
#define GA1 53248
#define GA2 53760
#define GSM 54272

__global__ __launch_bounds__(256) void k_gemm_tc(const float* __restrict__ X,
                                                 const float* __restrict__ W,
                                                 const float* __restrict__ a1,
                                                 const float* __restrict__ a2) {
    extern __shared__ char sm[];
    const uint32_t smb = smem_u32(sm);
    const int t = threadIdx.x, w = t >> 5, lane = t & 31;
    const int wm = w & 3, wn = w >> 2;
    const int row0 = blockIdx.x * 64;

    if (t < 128) {
        ((float*)(sm + GA1))[t] = a1[t];
        ((float*)(sm + GA2))[t] = a2[t];
    }

    float acc[8][4];
#pragma unroll
    for (int nt = 0; nt < 8; nt++)
        acc[nt][0] = acc[nt][1] = acc[nt][2] = acc[nt][3] = 0.f;

    const uint32_t ax_off =
        (uint32_t)(wm * 16 + ((lane >> 3) & 1) * 8 + (lane & 7)) * PX +
        (lane >> 4) * 16;
    const uint32_t wl_row = (uint32_t)lane * PW;

    for (int c = 0; c < 8; c++) {
        const int kc = c * 64;
#pragma unroll
        for (int l = 0; l < 4; l++) {
            int f = t + l * 256;
            int m = f >> 4, kq = (f & 15) * 4;
            float4 v = *(const float4*)(X + (size_t)(row0 + m) * FIN_ + kc + kq);
            uint32_t h0, l0, h1, l1;
            split2(v.x, v.y, h0, l0);
            split2(v.z, v.w, h1, l1);
            *(uint2*)(sm + GXH + m * PX + kq * 2) = make_uint2(h0, h1);
            *(uint2*)(sm + GXL + m * PX + kq * 2) = make_uint2(l0, l1);
        }
#pragma unroll
        for (int l = 0; l < 8; l++) {
            int f = t + l * 256;
            int k = f >> 5, nq = (f & 31) * 4;
            float4 v = *(const float4*)(W + (size_t)(kc + k) * FOUT_ + nq);
            uint32_t h0, l0, h1, l1;
            split2(v.x, v.y, h0, l0);
            split2(v.z, v.w, h1, l1);
            *(uint2*)(sm + GWH + k * PW + nq * 2) = make_uint2(h0, h1);
            *(uint2*)(sm + GWL + k * PW + nq * 2) = make_uint2(l0, l1);
        }
        __syncthreads();

        uint32_t ah[4][4], al[4][4];
#pragma unroll
        for (int ks = 0; ks < 4; ks++) {
            LDM4(ah[ks][0], ah[ks][1], ah[ks][2], ah[ks][3],
                 smb + GXH + ax_off + ks * 32);
            LDM4(al[ks][0], al[ks][1], al[ks][2], al[ks][3],
                 smb + GXL + ax_off + ks * 32);
        }
#pragma unroll
        for (int nt = 0; nt < 8; nt++) {
            const int n0 = wn * 64 + nt * 8;
            const uint32_t wadr = smb + GWH + wl_row + n0 * 2;
            uint32_t bh[8], bl[8];
            LDM4T(bh[0], bh[1], bh[2], bh[3], wadr);
            LDM4T(bh[4], bh[5], bh[6], bh[7], wadr + 32 * PW);
            LDM4T(bl[0], bl[1], bl[2], bl[3], wadr + (GWL - GWH));
            LDM4T(bl[4], bl[5], bl[6], bl[7], wadr + (GWL - GWH) + 32 * PW);
#pragma unroll
            for (int ks = 0; ks < 4; ks++) {
                mma_bf16(acc[nt], ah[ks][0], ah[ks][1], ah[ks][2], ah[ks][3],
                         bh[2 * ks], bh[2 * ks + 1]);
                mma_bf16(acc[nt], ah[ks][0], ah[ks][1], ah[ks][2], ah[ks][3],
                         bl[2 * ks], bl[2 * ks + 1]);
                mma_bf16(acc[nt], al[ks][0], al[ks][1], al[ks][2], al[ks][3],
                         bh[2 * ks], bh[2 * ks + 1]);
            }
        }
        __syncthreads();
    }

    // ---- epilogue ----
    const int g = lane >> 2, tig = lane & 3;
    float* Ds = (float*)sm;
    {
        const int r = wm * 16 + g, cl = wn * 64 + 2 * tig;
#pragma unroll
        for (int nt = 0; nt < 8; nt++) {
            Ds[r * 132 + cl + nt * 8]           = acc[nt][0];
            Ds[r * 132 + cl + nt * 8 + 1]       = acc[nt][1];
            Ds[(r + 8) * 132 + cl + nt * 8]     = acc[nt][2];
            Ds[(r + 8) * 132 + cl + nt * 8 + 1] = acc[nt][3];
        }
    }
    __syncthreads();
    const float* A1 = (const float*)(sm + GA1);
    const float* A2 = (const float*)(sm + GA2);
#pragma unroll
    for (int rr = 0; rr < 8; rr++) {
        int r = w * 8 + rr;
        float s1 = 0.f, s2 = 0.f;
#pragma unroll
        for (int q = 0; q < 4; q++) {
            float v = Ds[r * 132 + lane + 32 * q];
            s1 = fmaf(v, A1[lane + 32 * q], s1);
            s2 = fmaf(v, A2[lane + 32 * q], s2);
        }
#pragma unroll
        for (int o = 16; o; o >>= 1) {
            s1 += __shfl_down_sync(0xffffffffu, s1, o);
            s2 += __shfl_down_sync(0xffffffffu, s2, o);
        }
        if (lane == 0) {
            int gr = row0 + r;
            g_t1[gr] = s1;  g_t2[gr] = s2;
            g_e1h[gr] = __float2half_rn(0.25f * expf(s1));
            g_f1h[gr] = __float2half_rn(0.25f * expf(0.2f * s1));
            g_e2h[gr] = __float2half_rn(0.25f * expf(s2));
            g_f2h[gr] = __float2half_rn(0.25f * expf(0.2f * s2));
        }
    }
    __syncthreads();
    {
        const int o = t & 127, half = t >> 7;
        const int bb = row0 >> 11, j0g = row0 & (N_ - 1);
        uint32_t uH[16];
#pragma unroll
        for (int ii = 0; ii < 16; ii++) {
            int j0l = half * 32 + 2 * ii;
            uH[ii] = h2u(__floats2half2_rn(Ds[j0l * 132 + o],
                                           Ds[(j0l + 1) * 132 + o]));
        }
        size_t base = ((size_t)(bb * TROWS) + o) * N_ + j0g + half * 32;
#pragma unroll
        for (int q = 0; q < 4; q++)
            *(uint4*)(g_hH + base + q * 8) =
                make_uint4(uH[4 * q], uH[4 * q + 1], uH[4 * q + 2], uH[4 * q + 3]);
        if (t < 64)
            g_hH[((size_t)(bb * TROWS) + 128) * N_ + j0g + t] = __float2half_rn(1.0f);
    }
}

// ---------------------------------------------------------------------------
// K2: attention, single fp16-P GEMM [D|den] = P @ [h;1].
// Warp grid 2(m) x 4(n): halves redundant B-fragment ldmatrix traffic.
// Tiles: wn gets gt = wn*4 + 0..3; wn==3 additionally gt=16 (ones/den col).
// ---------------------------------------------------------------------------
#define ASTG (2 * TILE_B)           // 39168
#define APB  144
#define ASZ  (64 * APB)             // 9216
#define ST2  (ASTG + 2 * ASZ)       // 57600: t2 fp32 [1024]
#define SE2  (ST2 + 4096)           // 61696: 0.25*E2 fp16 [1024]
#define SF2  (SE2 + 2048)           // 63744: 0.25*F2 fp16 [1024]
#define ASM2 (SF2 + 2048)           // 65792 total dynamic

__global__ __launch_bounds__(256, 2) void k_attn_tc(const int* __restrict__ adj,
                                                    const int* __restrict__ d1p,
                                                    const int* __restrict__ d2p,
                                                    float* __restrict__ out) {
    extern __shared__ char sm[];
    __shared__ float s_den[64];
    __shared__ int s_old;
    const uint32_t smb = smem_u32(sm);
    const int t = threadIdx.x, w = t >> 5, lane = t & 31;
    const int g = lane >> 2, tig = lane & 3;
    const int wm = w & 1, wn = w >> 1;
    const int tile = blockIdx.x >> 1, jh = blockIdx.x & 1;
    const int b = tile >> 5, i0 = (tile & 31) * 64;
    const int jbase = jh * 1024;
    const int d1 = *d1p, d2 = *d2p;

    const __half* gHb = g_hH + (size_t)b * TROWS * N_;

    auto load_chunk = [&](int j0, int buf) {
#pragma unroll
        for (int l = 0; l < 5; l++) {
            int f = t + l * 256;
            if (f < 1088) {
                int row = f >> 3, u = f & 7;
                const __half* src = gHb + (size_t)row * N_ + j0 + u * 8;
                uint32_t dst = smb + buf * TILE_B + row * PB2 + u * 16;
                CPASYNC16(dst, src);
            }
        }
    };

    load_chunk(jbase, 0);
    CPCOMMIT();

    // ---- tables into smem ----
    ((float4*)(sm + ST2))[t] = ((const float4*)(g_t2 + b * N_ + jbase))[t];
    if (t < 128)
        ((uint4*)(sm + SE2))[t] = ((const uint4*)(g_e2h + b * N_ + jbase))[t];
    else
        ((uint4*)(sm + SF2))[t - 128] =
            ((const uint4*)(g_f2h + b * N_ + jbase))[t - 128];

    // ---- expansion row constants ----
    const int rexp = t >> 2, ctexp = t & 3;
    const int gadj = b * N_ + i0 + rexp;
    const float nt1r = -g_t1[gadj];
    const uint32_t e1lo = (uint32_t)__half_as_ushort(g_e1h[gadj]);
    const uint32_t f1lo = (uint32_t)__half_as_ushort(g_f1h[gadj]);
    const uint32_t e1hi = e1lo << 16, f1hi = f1lo << 16;
    const int* adjrow = adj + (size_t)gadj * N_ + jbase + ctexp * 16;

    auto expand = [&](int4 q0, int4 q1, int4 q2, int4 q3, int cc, int ab) {
        const int jl = cc * 64 + ctexp * 16;
        const float* tp = (const float*)(sm + ST2) + jl;
        float4 t0 = *(const float4*)(tp);
        float4 t1v = *(const float4*)(tp + 4);
        float4 t2v = *(const float4*)(tp + 8);
        float4 t3 = *(const float4*)(tp + 12);
        float tf[16] = {t0.x, t0.y, t0.z, t0.w, t1v.x, t1v.y, t1v.z, t1v.w,
                        t2v.x, t2v.y, t2v.z, t2v.w, t3.x, t3.y, t3.z, t3.w};
        uint4 ea = *(const uint4*)((const __half*)(sm + SE2) + jl);
        uint4 eb = *(const uint4*)((const __half*)(sm + SE2) + jl + 8);
        uint4 fa = *(const uint4*)((const __half*)(sm + SF2) + jl);
        uint4 fb = *(const uint4*)((const __half*)(sm + SF2) + jl + 8);
        uint32_t UE[8] = {ea.x, ea.y, ea.z, ea.w, eb.x, eb.y, eb.z, eb.w};
        uint32_t UF[8] = {fa.x, fa.y, fa.z, fa.w, fb.x, fb.y, fb.z, fb.w};
        int av[16] = {q0.x, q0.y, q0.z, q0.w, q1.x, q1.y, q1.z, q1.w,
                      q2.x, q2.y, q2.z, q2.w, q3.x, q3.y, q3.z, q3.w};
        uint32_t ow[8];
#pragma unroll
        for (int k = 0; k < 8; k++) {
            int a0 = av[2 * k], a1 = av[2 * k + 1];
            bool m0 = (a0 == d1) | (a0 == d2);
            bool m1 = (a1 == d1) | (a1 == d2);
            bool p0 = tf[2 * k] > nt1r;
            bool p1 = tf[2 * k + 1] > nt1r;
            uint32_t s2 = (p0 ? (UE[k] & 0xffffu) : (UF[k] & 0xffffu))
                        | (p1 ? (UE[k] & 0xffff0000u) : (UF[k] & 0xffff0000u));
            uint32_t s1 = (p0 ? e1lo : f1lo) | (p1 ? e1hi : f1hi);
            __half2 pr = __hmul2(*(__half2*)&s1, *(__half2*)&s2);
            uint32_t z = (m0 ? 0xffffu : 0u) | (m1 ? 0xffff0000u : 0u);
            ow[k] = (*(uint32_t*)&pr) & z;
        }
        char* dst = sm + ASTG + ab * ASZ + rexp * APB + ctexp * 32;
        *(uint4*)(dst)      = make_uint4(ow[0], ow[1], ow[2], ow[3]);
        *(uint4*)(dst + 16) = make_uint4(ow[4], ow[5], ow[6], ow[7]);
    };

    int4 q0 = *(const int4*)(adjrow);
    int4 q1 = *(const int4*)(adjrow + 4);
    int4 q2 = *(const int4*)(adjrow + 8);
    int4 q3 = *(const int4*)(adjrow + 12);

    __syncthreads();
    expand(q0, q1, q2, q3, 0, 0);

    const int ntiles = (wn == 3) ? 5 : 4;
    float acc[2][5][4];
#pragma unroll
    for (int ms = 0; ms < 2; ms++)
#pragma unroll
        for (int k = 0; k < 5; k++)
            acc[ms][k][0] = acc[ms][k][1] = acc[ms][k][2] = acc[ms][k][3] = 0.f;

    const uint32_t bloff = (uint32_t)(lane & 7) * PB2 + (lane >> 3) * 16;
    const uint32_t aloff =
        (uint32_t)((lane & 15) + wm * 32) * APB + (lane >> 4) * 16;

    for (int c = 0; c < 16; c++) {
        const int buf = c & 1;
        CPWAIT(0);
        __syncthreads();
        if (c + 1 < 16) {
            load_chunk(jbase + (c + 1) * 64, buf ^ 1);
            CPCOMMIT();
            const int* ap = adjrow + (c + 1) * 64;
            q0 = *(const int4*)(ap);
            q1 = *(const int4*)(ap + 4);
            q2 = *(const int4*)(ap + 8);
            q3 = *(const int4*)(ap + 12);
        }

        const uint32_t abase = smb + ASTG + buf * ASZ + aloff;
        const uint32_t base = smb + buf * TILE_B + bloff;
#pragma unroll
        for (int ga = 0; ga < 2; ga++) {
            // A-frags: 2 m-sets x 2 k-steps
            uint32_t aH[2][2][4];
#pragma unroll
            for (int ms = 0; ms < 2; ms++)
#pragma unroll
                for (int k2 = 0; k2 < 2; k2++)
                    LDM4(aH[ms][k2][0], aH[ms][k2][1], aH[ms][k2][2], aH[ms][k2][3],
                         abase + (uint32_t)(ms * 16) * APB + (2 * ga + k2) * 32);

            // B-frags: my tiles, pipelined
            uint32_t bb[2][4];
            {
                const int gt0 = wn * 4;
                LDM4(bb[0][0], bb[0][1], bb[0][2], bb[0][3],
                     base + (uint32_t)(gt0 * 8) * PB2 + ga * 64);
            }
#pragma unroll
            for (int k = 0; k < 5; k++) {
                if (k >= ntiles) break;
                const int cur = k & 1, nxt = cur ^ 1;
                if (k + 1 < ntiles) {
                    const int gtn = (k + 1 < 4) ? wn * 4 + k + 1 : 16;
                    LDM4(bb[nxt][0], bb[nxt][1], bb[nxt][2], bb[nxt][3],
                         base + (uint32_t)(gtn * 8) * PB2 + ga * 64);
                }
                mma_f16(acc[0][k], aH[0][0][0], aH[0][0][1], aH[0][0][2], aH[0][0][3],
                        bb[cur][0], bb[cur][1]);
                mma_f16(acc[1][k], aH[1][0][0], aH[1][0][1], aH[1][0][2], aH[1][0][3],
                        bb[cur][0], bb[cur][1]);
                mma_f16(acc[0][k], aH[0][1][0], aH[0][1][1], aH[0][1][2], aH[0][1][3],
                        bb[cur][2], bb[cur][3]);
                mma_f16(acc[1][k], aH[1][1][0], aH[1][1][1], aH[1][1][2], aH[1][1][3],
                        bb[cur][2], bb[cur][3]);
            }
        }

        if (c + 1 < 16)
            expand(q0, q1, q2, q3, c + 1, buf ^ 1);
    }

    // local rows for this warp: wm*32 + ms*16 + g (and +8)
    // ---- partial denominators: tile 16 (wn==3, k=4), elems 0/2 ----
    if (wn == 3 && tig == 0) {
#pragma unroll
        for (int ms = 0; ms < 2; ms++) {
            s_den[wm * 32 + ms * 16 + g]     = acc[ms][4][0];
            s_den[wm * 32 + ms * 16 + g + 8] = acc[ms][4][2];
        }
    }
    __syncthreads();

    float* gp = g_part[jh];
#pragma unroll
    for (int ms = 0; ms < 2; ms++) {
        const int gr0 = b * N_ + i0 + wm * 32 + ms * 16 + g;
        const int gr1 = gr0 + 8;
#pragma unroll
        for (int k = 0; k < 4; k++) {
            const int cl = (wn * 4 + k) * 8 + 2 * tig;
            *(float2*)(gp + (size_t)gr0 * FOUT_ + cl) =
                make_float2(acc[ms][k][0], acc[ms][k][1]);
            *(float2*)(gp + (size_t)gr1 * FOUT_ + cl) =
                make_float2(acc[ms][k][2], acc[ms][k][3]);
        }
    }
    if (t < 64) g_den[jh][b * N_ + i0 + t] = s_den[t];
    __threadfence();
    __syncthreads();
    if (t == 0) s_old = atomicAdd(&g_cnt[tile], 1);
    __syncthreads();

    if (s_old == 1) {
        __threadfence();
        const float* go = g_part[jh ^ 1];
        const float* gdo = g_den[jh ^ 1];
#pragma unroll
        for (int ms = 0; ms < 2; ms++) {
            const int lr0 = wm * 32 + ms * 16 + g;
            const int gr0 = b * N_ + i0 + lr0;
            const int gr1 = gr0 + 8;
            const float inv0 = 1.0f / (s_den[lr0] + gdo[gr0]);
            const float inv1 = 1.0f / (s_den[lr0 + 8] + gdo[gr1]);
#pragma unroll
            for (int k = 0; k < 4; k++) {
                const int cl = (wn * 4 + k) * 8 + 2 * tig;
                float2 o0 = *(const float2*)(go + (size_t)gr0 * FOUT_ + cl);
                float2 o1 = *(const float2*)(go + (size_t)gr1 * FOUT_ + cl);
                *(float2*)(out + (size_t)gr0 * FOUT_ + cl) =
                    make_float2((acc[ms][k][0] + o0.x) * inv0,
                                (acc[ms][k][1] + o0.y) * inv0);
                *(float2*)(out + (size_t)gr1 * FOUT_ + cl) =
                    make_float2((acc[ms][k][2] + o1.x) * inv1,
                                (acc[ms][k][3] + o1.y) * inv1);
            }
        }
        if (t == 0) g_cnt[tile] = 0;
    }
}

// ---------------------------------------------------------------------------
extern "C" void kernel_launch(void* const* d_in, const int* in_sizes, int n_in,
                              void* d_out, int out_size) {
    const float* X   = (const float*)d_in[0];
    const float* W   = (const float*)d_in[1];
    const float* a1  = (const float*)d_in[2];
    const float* a2  = (const float*)d_in[3];
    const int*   adj = (const int*)d_in[4];
    // d_in[5] = adj_tree: unused by the reference forward
    const int* d1p = (const int*)d_in[6];
    const int* d2p = (const int*)d_in[7];
    float* out = (float*)d_out;

    cudaFuncSetAttribute(k_gemm_tc, cudaFuncAttributeMaxDynamicSharedMemorySize, GSM);
    k_gemm_tc<<<ROWS_TOT / 64, 256, GSM>>>(X, W, a1, a2);

    cudaFuncSetAttribute(k_attn_tc, cudaFuncAttributeMaxDynamicSharedMemorySize, ASM2);
    k_attn_tc<<<B_ * 32 * 2, 256, ASM2>>>(adj, d1p, d2p, out);
}